// round 1
// baseline (speedup 1.0000x reference)
#include <cuda_runtime.h>

#define BN_EPS 1e-5f

// ---------------- persistent scratch (device globals; no allocations) -----------
__device__ float d_h1[8192 * 64];
__device__ float d_h2[8192 * 256];
__device__ int   d_idx[8192 * 8];
__device__ float d_Q[8192 * 1024];
__device__ float d_R[8192 * 1024];
__device__ float d_l0[8192 * 512];
__device__ float d_big1[65536 * 1024];   // 256 MB
__device__ float d_big2[65536 * 1024];   // 256 MB
__device__ float d_sum[1024];
__device__ float d_ss[1024];

// ---------------- tiny first layer: out = xyz @ W1^T  (8192x3 @ 3x64) ----------
__global__ void lin1_kernel(const float* __restrict__ xyz,
                            const float* __restrict__ W1,
                            float* __restrict__ out) {
    int t = blockIdx.x * blockDim.x + threadIdx.x;   // 8192*64 threads
    int r = t >> 6;
    int o = t & 63;
    float x0 = xyz[r * 3 + 0], x1 = xyz[r * 3 + 1], x2 = xyz[r * 3 + 2];
    out[t] = x0 * W1[o * 3 + 0] + x1 * W1[o * 3 + 1] + x2 * W1[o * 3 + 2];
}

// ---------------- zero the stats accumulators -----------------------------------
__global__ void zero_stats_kernel(float* __restrict__ s, float* __restrict__ q) {
    int t = blockIdx.x * blockDim.x + threadIdx.x;
    if (t < 1024) { s[t] = 0.f; q[t] = 0.f; }
}

// ---------------- per-column sum / sumsq over M rows ----------------------------
// grid: (M/512, ceil(C/256)), 256 threads
__global__ void colstats_kernel(const float* __restrict__ x, int M, int C,
                                float* __restrict__ sum, float* __restrict__ ss) {
    int c = blockIdx.y * blockDim.x + threadIdx.x;
    if (c >= C) return;
    size_t r0 = (size_t)blockIdx.x * 512;
    const float* p = x + r0 * C + c;
    float s = 0.f, q = 0.f;
    for (int r = 0; r < 512; r++) {
        float v = p[(size_t)r * C];
        s += v;
        q += v * v;
    }
    atomicAdd(&sum[c], s);
    atomicAdd(&ss[c], q);
}

// ---------------- in-place BN + ReLU (vectorized float4) ------------------------
__global__ void bn_relu_kernel(float* __restrict__ x,
                               const float* __restrict__ sum, const float* __restrict__ ss,
                               const float* __restrict__ g, const float* __restrict__ bta,
                               int M, int C) {
    int t = blockIdx.x * blockDim.x + threadIdx.x;
    int C4 = C >> 2;
    if (t >= M * C4) return;
    int c = (t % C4) << 2;
    float invM = 1.0f / (float)M;
    float4 v = ((float4*)x)[t];
    float4 o;
    {
        float m = sum[c + 0] * invM; float var = ss[c + 0] * invM - m * m;
        float sc = g[c + 0] * rsqrtf(var + BN_EPS);
        o.x = fmaxf((v.x - m) * sc + bta[c + 0], 0.f);
    }
    {
        float m = sum[c + 1] * invM; float var = ss[c + 1] * invM - m * m;
        float sc = g[c + 1] * rsqrtf(var + BN_EPS);
        o.y = fmaxf((v.y - m) * sc + bta[c + 1], 0.f);
    }
    {
        float m = sum[c + 2] * invM; float var = ss[c + 2] * invM - m * m;
        float sc = g[c + 2] * rsqrtf(var + BN_EPS);
        o.z = fmaxf((v.z - m) * sc + bta[c + 2], 0.f);
    }
    {
        float m = sum[c + 3] * invM; float var = ss[c + 3] * invM - m * m;
        float sc = g[c + 3] * rsqrtf(var + BN_EPS);
        o.w = fmaxf((v.w - m) * sc + bta[c + 3], 0.f);
    }
    ((float4*)x)[t] = o;
}

// ---------------- BN + ReLU + max over k=8 (optionally transposed output) -------
// x: (8192*8, C); out: (8192, C) or transposed (B, C, N)
__global__ void bn_relu_max_kernel(const float* __restrict__ x,
                                   const float* __restrict__ sum, const float* __restrict__ ss,
                                   const float* __restrict__ g, const float* __restrict__ bta,
                                   float* __restrict__ out, int C, int transposed) {
    int t = blockIdx.x * blockDim.x + threadIdx.x;   // 8192*C threads
    if (t >= 8192 * C) return;
    int c = t % C;
    int bn = t / C;
    const float invM = 1.0f / 65536.0f;
    float m  = sum[c] * invM;
    float var = ss[c] * invM - m * m;
    float sc = g[c] * rsqrtf(var + BN_EPS);
    float bb = bta[c];
    const float* p = x + (size_t)bn * 8 * C + c;
    float best = -3.4e38f;
#pragma unroll
    for (int k = 0; k < 8; k++) {
        float v = p[(size_t)k * C];
        best = fmaxf(best, (v - m) * sc + bb);
    }
    best = fmaxf(best, 0.f);   // relu(max) == max(relu)
    if (transposed) {
        int b = bn >> 10;
        int n = bn & 1023;
        out[((size_t)b * C + c) * 1024 + n] = best;
    } else {
        out[t] = best;
    }
}

// ---------------- kNN: k=8 smallest (d2, idx) per query, stable ties ------------
// grid: dim3(4, 8), 256 threads
__global__ void knn_kernel(const float* __restrict__ xyz, int* __restrict__ idx) {
    __shared__ float sx[1024], sy[1024], sz[1024], sq[1024];
    int b = blockIdx.y;
    int tid = threadIdx.x;
    for (int i = tid; i < 1024; i += 256) {
        float x = xyz[((b << 10) + i) * 3 + 0];
        float y = xyz[((b << 10) + i) * 3 + 1];
        float z = xyz[((b << 10) + i) * 3 + 2];
        sx[i] = x; sy[i] = y; sz[i] = z;
        sq[i] = x * x + y * y + z * z;
    }
    __syncthreads();
    int n = blockIdx.x * 256 + tid;
    float qx = sx[n], qy = sy[n], qz = sz[n], qs = sq[n];
    float bd[8]; int bi[8];
#pragma unroll
    for (int j = 0; j < 8; j++) { bd[j] = 3.4e38f; bi[j] = 0; }
    for (int m = 0; m < 1024; m++) {
        float d2 = qs + sq[m] - 2.f * (qx * sx[m] + qy * sy[m] + qz * sz[m]);
        if (d2 < bd[7]) {           // strict < : equal keys keep earlier index (stable)
            bd[7] = d2; bi[7] = m;
#pragma unroll
            for (int j = 7; j > 0; j--) {
                if (bd[j] < bd[j - 1]) {
                    float td = bd[j]; bd[j] = bd[j - 1]; bd[j - 1] = td;
                    int ti = bi[j]; bi[j] = bi[j - 1]; bi[j - 1] = ti;
                }
            }
        }
    }
#pragma unroll
    for (int j = 0; j < 8; j++) idx[((b << 10) + n) * 8 + j] = bi[j];
}

// ---------------- gather-expand: out[row,:] = Q[idx[row]] - Q[center] + R[center]
__global__ void expand_kernel(const float4* __restrict__ Q, const float4* __restrict__ R,
                              const int* __restrict__ idx, float4* __restrict__ out, int C4) {
    int t = blockIdx.x * blockDim.x + threadIdx.x;   // 65536*C4 threads
    if (t >= 65536 * C4) return;
    int c4 = t % C4;
    int row = t / C4;            // (b*1024 + n)*8 + k
    int bn = row >> 3;
    int b = bn >> 10;
    int nb = idx[row];
    int src = (b << 10) + nb;
    float4 q  = Q[src * C4 + c4];
    float4 qc = Q[bn * C4 + c4];
    float4 r  = R[bn * C4 + c4];
    float4 o;
    o.x = q.x - qc.x + r.x;
    o.y = q.y - qc.y + r.y;
    o.z = q.z - qc.z + r.z;
    o.w = q.w - qc.w + r.w;
    out[t] = o;
}

// ---------------- fp32 SGEMM  C[M,N] = A[M,K] @ B[N,K]^T ------------------------
// 128x128 tile, BK=16, 256 threads, 8x8 per thread. M,N multiples of 128, K of 16.
__global__ void __launch_bounds__(256, 2)
gemm_nt_kernel(const float* __restrict__ A, int lda,
               const float* __restrict__ B, int ldb,
               float* __restrict__ C, int ldc, int K) {
    __shared__ float As[16][128];
    __shared__ float Bs[16][128];
    int tid = threadIdx.x;
    int bm = blockIdx.y * 128;
    int bn = blockIdx.x * 128;
    int lr = tid >> 2;           // 0..63
    int lc = (tid & 3) << 2;     // 0,4,8,12
    int tx = tid & 15;
    int ty = tid >> 4;
    const float* Ap  = A + (size_t)(bm + lr) * lda + lc;
    const float* Ap2 = A + (size_t)(bm + lr + 64) * lda + lc;
    const float* Bp  = B + (size_t)(bn + lr) * ldb + lc;
    const float* Bp2 = B + (size_t)(bn + lr + 64) * ldb + lc;

    float acc[8][8];
#pragma unroll
    for (int i = 0; i < 8; i++)
#pragma unroll
        for (int j = 0; j < 8; j++) acc[i][j] = 0.f;

    for (int k0 = 0; k0 < K; k0 += 16) {
        float4 a0 = *(const float4*)(Ap + k0);
        float4 a1 = *(const float4*)(Ap2 + k0);
        float4 b0 = *(const float4*)(Bp + k0);
        float4 b1 = *(const float4*)(Bp2 + k0);
        __syncthreads();
        As[lc + 0][lr] = a0.x; As[lc + 1][lr] = a0.y; As[lc + 2][lr] = a0.z; As[lc + 3][lr] = a0.w;
        As[lc + 0][lr + 64] = a1.x; As[lc + 1][lr + 64] = a1.y; As[lc + 2][lr + 64] = a1.z; As[lc + 3][lr + 64] = a1.w;
        Bs[lc + 0][lr] = b0.x; Bs[lc + 1][lr] = b0.y; Bs[lc + 2][lr] = b0.z; Bs[lc + 3][lr] = b0.w;
        Bs[lc + 0][lr + 64] = b1.x; Bs[lc + 1][lr + 64] = b1.y; Bs[lc + 2][lr + 64] = b1.z; Bs[lc + 3][lr + 64] = b1.w;
        __syncthreads();
#pragma unroll
        for (int kk = 0; kk < 16; kk++) {
            float4 aA = *(const float4*)&As[kk][ty * 8];
            float4 aB = *(const float4*)&As[kk][ty * 8 + 4];
            float4 bA = *(const float4*)&Bs[kk][tx * 8];
            float4 bB = *(const float4*)&Bs[kk][tx * 8 + 4];
            float av[8] = {aA.x, aA.y, aA.z, aA.w, aB.x, aB.y, aB.z, aB.w};
            float bv[8] = {bA.x, bA.y, bA.z, bA.w, bB.x, bB.y, bB.z, bB.w};
#pragma unroll
            for (int i = 0; i < 8; i++)
#pragma unroll
                for (int j = 0; j < 8; j++)
                    acc[i][j] += av[i] * bv[j];
        }
    }
#pragma unroll
    for (int i = 0; i < 8; i++) {
        float* cp = C + (size_t)(bm + ty * 8 + i) * ldc + bn + tx * 8;
        float4 c0 = {acc[i][0], acc[i][1], acc[i][2], acc[i][3]};
        float4 c1 = {acc[i][4], acc[i][5], acc[i][6], acc[i][7]};
        *(float4*)cp = c0;
        *(float4*)(cp + 4) = c1;
    }
}

// ---------------- host orchestration --------------------------------------------
static inline int ceil_div(int a, int b) { return (a + b - 1) / b; }

extern "C" void kernel_launch(void* const* d_in, const int* in_sizes, int n_in,
                              void* d_out, int out_size) {
    const float* xyz = (const float*)d_in[0];
    const float* W1  = (const float*)d_in[1];
    const float* g1  = (const float*)d_in[2];
    const float* b1  = (const float*)d_in[3];
    const float* W2  = (const float*)d_in[4];
    const float* g2  = (const float*)d_in[5];
    const float* b2  = (const float*)d_in[6];
    const float* WA1 = (const float*)d_in[7];
    const float* gA1 = (const float*)d_in[8];
    const float* bA1 = (const float*)d_in[9];
    const float* WA2 = (const float*)d_in[10];
    const float* gA2 = (const float*)d_in[11];
    const float* bA2 = (const float*)d_in[12];
    const float* WB1 = (const float*)d_in[13];
    const float* gB1 = (const float*)d_in[14];
    const float* bB1 = (const float*)d_in[15];
    const float* WB2 = (const float*)d_in[16];
    const float* gB2 = (const float*)d_in[17];
    const float* bB2 = (const float*)d_in[18];
    float* out = (float*)d_out;

    float *h1, *h2, *Q, *R, *l0, *big1, *big2, *sumb, *ssb;
    int* idx;
    cudaGetSymbolAddress((void**)&h1,   d_h1);
    cudaGetSymbolAddress((void**)&h2,   d_h2);
    cudaGetSymbolAddress((void**)&idx,  d_idx);
    cudaGetSymbolAddress((void**)&Q,    d_Q);
    cudaGetSymbolAddress((void**)&R,    d_R);
    cudaGetSymbolAddress((void**)&l0,   d_l0);
    cudaGetSymbolAddress((void**)&big1, d_big1);
    cudaGetSymbolAddress((void**)&big2, d_big2);
    cudaGetSymbolAddress((void**)&sumb, d_sum);
    cudaGetSymbolAddress((void**)&ssb,  d_ss);

    const int T = 256;

    // ---- layer 1: h1 = bn_relu(xyz @ W1^T)   (8192 x 64) ----
    lin1_kernel<<<8192 * 64 / T, T>>>(xyz, W1, h1);
    zero_stats_kernel<<<4, T>>>(sumb, ssb);
    colstats_kernel<<<dim3(8192 / 512, 1), T>>>(h1, 8192, 64, sumb, ssb);
    bn_relu_kernel<<<8192 * 16 / T, T>>>(h1, sumb, ssb, g1, b1, 8192, 64);

    // ---- layer 2: h2 = bn_relu(h1 @ W2^T)    (8192 x 256) ----
    gemm_nt_kernel<<<dim3(2, 64), T>>>(h1, 64, W2, 64, h2, 256, 64);
    zero_stats_kernel<<<4, T>>>(sumb, ssb);
    colstats_kernel<<<dim3(8192 / 512, 1), T>>>(h2, 8192, 256, sumb, ssb);
    bn_relu_kernel<<<8192 * 64 / T, T>>>(h2, sumb, ssb, g2, b2, 8192, 256);

    // ---- kNN (k = 8) ----
    knn_kernel<<<dim3(4, 8), T>>>(xyz, idx);

    // ---- local_op A, GEMM1 via gather trick: Q = h2@Wg^T, R = h2@Wc^T ----
    gemm_nt_kernel<<<dim3(4, 64), T>>>(h2, 256, WA1,       512, Q, 512, 256);
    gemm_nt_kernel<<<dim3(4, 64), T>>>(h2, 256, WA1 + 256, 512, R, 512, 256);
    expand_kernel<<<65536 * 128 / T, T>>>((const float4*)Q, (const float4*)R, idx,
                                          (float4*)big1, 128);
    zero_stats_kernel<<<4, T>>>(sumb, ssb);
    colstats_kernel<<<dim3(65536 / 512, 2), T>>>(big1, 65536, 512, sumb, ssb);
    bn_relu_kernel<<<65536 * 128 / T, T>>>(big1, sumb, ssb, gA1, bA1, 65536, 512);

    // ---- local_op A, GEMM2 + bn_relu + max_k -> l0 (8192 x 512) ----
    gemm_nt_kernel<<<dim3(4, 512), T>>>(big1, 512, WA2, 512, big2, 512, 512);
    zero_stats_kernel<<<4, T>>>(sumb, ssb);
    colstats_kernel<<<dim3(65536 / 512, 2), T>>>(big2, 65536, 512, sumb, ssb);
    bn_relu_max_kernel<<<8192 * 512 / T, T>>>(big2, sumb, ssb, gA2, bA2, l0, 512, 0);

    // ---- local_op B, GEMM1 via gather trick ----
    gemm_nt_kernel<<<dim3(8, 64), T>>>(l0, 512, WB1,       1024, Q, 1024, 512);
    gemm_nt_kernel<<<dim3(8, 64), T>>>(l0, 512, WB1 + 512, 1024, R, 1024, 512);
    expand_kernel<<<65536 * 256 / T, T>>>((const float4*)Q, (const float4*)R, idx,
                                          (float4*)big1, 256);
    zero_stats_kernel<<<4, T>>>(sumb, ssb);
    colstats_kernel<<<dim3(65536 / 512, 4), T>>>(big1, 65536, 1024, sumb, ssb);
    bn_relu_kernel<<<65536 * 256 / T, T>>>(big1, sumb, ssb, gB1, bB1, 65536, 1024);

    // ---- local_op B, GEMM2 + bn_relu + max_k + transpose -> out (8,1024,1024) ----
    gemm_nt_kernel<<<dim3(8, 512), T>>>(big1, 1024, WB2, 1024, big2, 1024, 1024);
    zero_stats_kernel<<<4, T>>>(sumb, ssb);
    colstats_kernel<<<dim3(65536 / 512, 4), T>>>(big2, 65536, 1024, sumb, ssb);
    bn_relu_max_kernel<<<8192 * 1024 / T, T>>>(big2, sumb, ssb, gB2, bB2, out, 1024, 1);
}

// round 3
// speedup vs baseline: 1.9630x; 1.9630x over previous
#include <cuda_runtime.h>
#include <cuda_fp16.h>
#include <cstdint>

#define BN_EPS 1e-5f

// ================= persistent scratch (device globals; no allocations) ==========
__device__ float d_h1[8192 * 64];
__device__ __half d_h1h[8192 * 64], d_h1l[8192 * 64];
__device__ float d_h2[8192 * 256];
__device__ __half d_h2h[8192 * 256], d_h2l[8192 * 256];
__device__ int   d_idx[8192 * 8];
__device__ float d_Q[8192 * 1024];
__device__ float d_R[8192 * 1024];
__device__ float d_l0[8192 * 512];
__device__ __half d_l0h[8192 * 512], d_l0l[8192 * 512];
__device__ float d_big[65536 * 1024];                 // 256 MB fp32 scratch
__device__ __half d_Ah[65536 * 1024];                 // 128 MB fp16 hi
__device__ __half d_Al[65536 * 1024];                 // 128 MB fp16 lo
__device__ __half d_W2h[256 * 64],     d_W2l[256 * 64];
__device__ __half d_WA1h[512 * 512],   d_WA1l[512 * 512];
__device__ __half d_WA2h[512 * 512],   d_WA2l[512 * 512];
__device__ __half d_WB1h[1024 * 1024], d_WB1l[1024 * 1024];
__device__ __half d_WB2h[1024 * 1024], d_WB2l[1024 * 1024];
__device__ float d_sum[1024];
__device__ float d_ss[1024];

// ================= PTX helpers (arch-neutral, sm_80+) ===========================
__device__ __forceinline__ uint32_t smem_u32(const void* p) {
    uint32_t a;
    asm("{ .reg .u64 t; cvta.to.shared.u64 t, %1; cvt.u32.u64 %0, t; }" : "=r"(a) : "l"(p));
    return a;
}
__device__ __forceinline__ void cpa16(uint32_t s, const void* g) {
    asm volatile("cp.async.cg.shared.global [%0], [%1], 16;" :: "r"(s), "l"(g));
}
#define CP_COMMIT() asm volatile("cp.async.commit_group;" ::: "memory")
#define CP_WAIT0()  asm volatile("cp.async.wait_group 0;" ::: "memory")
#define CP_WAIT1()  asm volatile("cp.async.wait_group 1;" ::: "memory")

#define LDSM4(r0, r1, r2, r3, a) \
    asm volatile("ldmatrix.sync.aligned.m8n8.x4.shared.b16 {%0,%1,%2,%3}, [%4];" \
                 : "=r"(r0), "=r"(r1), "=r"(r2), "=r"(r3) : "r"(a))

#define MMA16816(c, a, b) \
    asm volatile("mma.sync.aligned.m16n8k16.row.col.f32.f16.f16.f32 " \
                 "{%0,%1,%2,%3}, {%4,%5,%6,%7}, {%8,%9}, {%0,%1,%2,%3};" \
                 : "+f"((c)[0]), "+f"((c)[1]), "+f"((c)[2]), "+f"((c)[3]) \
                 : "r"((a)[0]), "r"((a)[1]), "r"((a)[2]), "r"((a)[3]), \
                   "r"((b)[0]), "r"((b)[1]))

// ================= HMMA split-fp16 GEMM =========================================
// C[M,N](fp32) = (Ah+Al)[M,K] @ (Bh+Bl)[N,K]^T  via 3 fp16 products (AlBl dropped).
// CTA tile 128x128, BK=32, 2-stage cp.async pipeline, 8 warps of 32(m)x64(n).
// Smem rows padded to 40 halves (80B) -> ldmatrix conflict-free.
// Optional fused per-column sum / sum-of-squares (BN batch stats).
#define GBK 32
#define GMT_B 10240                   // bytes per matrix tile (128 * 80)
#define GSTAGE 40960                  // Ah|Al|Bh|Bl
#define GSMEM_DYN 81920

__global__ void __launch_bounds__(256, 1)
gemm_hmma_kernel(const __half* __restrict__ Ah, const __half* __restrict__ Al, int lda,
                 const __half* __restrict__ Bh, const __half* __restrict__ Bl, int ldb,
                 float* __restrict__ C, int ldc, int K,
                 float* __restrict__ gsum, float* __restrict__ gss) {
    extern __shared__ char smem[];
    __shared__ float s_sum[128], s_ss[128];
    const int tid = threadIdx.x;
    const int lane = tid & 31, wid = tid >> 5;
    const int wm = wid & 3, wn = wid >> 2;           // 4 x 2 warp grid
    const int bm = blockIdx.y * 128, bn = blockIdx.x * 128;
    const uint32_t sb = smem_u32(smem);

    if (gsum && tid < 128) { s_sum[tid] = 0.f; s_ss[tid] = 0.f; }

    float acc[2][8][4];
#pragma unroll
    for (int i = 0; i < 2; i++)
#pragma unroll
        for (int j = 0; j < 8; j++)
#pragma unroll
            for (int v = 0; v < 4; v++) acc[i][j][v] = 0.f;

    // cp.async mapping: per matrix 512 x 16B chunks, 2 per thread
    const int r0 = tid >> 2, cg0 = tid & 3;
    const int r1 = (tid + 256) >> 2, cg1 = tid & 3;
    const uint32_t so0 = (uint32_t)(r0 * 80 + cg0 * 16);
    const uint32_t so1 = (uint32_t)(r1 * 80 + cg1 * 16);

    // ldmatrix base addresses (stage 0)
    const uint32_t a_off = (uint32_t)((wm * 32 + (lane & 15)) * 80 + (lane >> 4) * 16);
    const int b_n = wn * 64 + (lane & 7) + ((lane >> 4) << 3);
    const uint32_t b_koff = (uint32_t)(((lane >> 3) & 1) * 16);

    const int NC = K / GBK;

    // prologue: stage 0
    {
        size_t ga0 = (size_t)(bm + r0) * lda + cg0 * 8;
        size_t ga1 = (size_t)(bm + r1) * lda + cg1 * 8;
        size_t gb0 = (size_t)(bn + r0) * ldb + cg0 * 8;
        size_t gb1 = (size_t)(bn + r1) * ldb + cg1 * 8;
        cpa16(sb + so0, Ah + ga0);               cpa16(sb + so1, Ah + ga1);
        cpa16(sb + GMT_B + so0, Al + ga0);       cpa16(sb + GMT_B + so1, Al + ga1);
        cpa16(sb + 2 * GMT_B + so0, Bh + gb0);   cpa16(sb + 2 * GMT_B + so1, Bh + gb1);
        cpa16(sb + 3 * GMT_B + so0, Bl + gb0);   cpa16(sb + 3 * GMT_B + so1, Bl + gb1);
    }
    CP_COMMIT();

    for (int c = 0; c < NC; c++) {
        if (c + 1 < NC) {
            uint32_t st = sb + (uint32_t)((c + 1) & 1) * GSTAGE;
            int kc = (c + 1) * GBK;
            size_t ga0 = (size_t)(bm + r0) * lda + kc + cg0 * 8;
            size_t ga1 = (size_t)(bm + r1) * lda + kc + cg1 * 8;
            size_t gb0 = (size_t)(bn + r0) * ldb + kc + cg0 * 8;
            size_t gb1 = (size_t)(bn + r1) * ldb + kc + cg1 * 8;
            cpa16(st + so0, Ah + ga0);               cpa16(st + so1, Ah + ga1);
            cpa16(st + GMT_B + so0, Al + ga0);       cpa16(st + GMT_B + so1, Al + ga1);
            cpa16(st + 2 * GMT_B + so0, Bh + gb0);   cpa16(st + 2 * GMT_B + so1, Bh + gb1);
            cpa16(st + 3 * GMT_B + so0, Bl + gb0);   cpa16(st + 3 * GMT_B + so1, Bl + gb1);
            CP_COMMIT();
            CP_WAIT1();
        } else {
            CP_WAIT0();
        }
        __syncthreads();

        uint32_t st = sb + (uint32_t)(c & 1) * GSTAGE;
#pragma unroll
        for (int kk = 0; kk < 2; kk++) {              // two k16 steps in BK=32
            uint32_t kb = (uint32_t)(kk * 32);        // bytes
            uint32_t ah[2][4], al[2][4], bh[8][2], bl[8][2];
#pragma unroll
            for (int mt = 0; mt < 2; mt++) {
                uint32_t aa = st + a_off + (uint32_t)(mt * 16 * 80) + kb;
                LDSM4(ah[mt][0], ah[mt][1], ah[mt][2], ah[mt][3], aa);
                LDSM4(al[mt][0], al[mt][1], al[mt][2], al[mt][3], aa + GMT_B);
            }
#pragma unroll
            for (int p = 0; p < 4; p++) {
                uint32_t ba = st + 2 * GMT_B +
                              (uint32_t)((b_n + p * 16) * 80) + b_koff + kb;
                LDSM4(bh[2 * p][0], bh[2 * p][1], bh[2 * p + 1][0], bh[2 * p + 1][1], ba);
                LDSM4(bl[2 * p][0], bl[2 * p][1], bl[2 * p + 1][0], bl[2 * p + 1][1],
                      ba + GMT_B);
            }
#pragma unroll
            for (int mt = 0; mt < 2; mt++)
#pragma unroll
                for (int nt = 0; nt < 8; nt++) {
                    MMA16816(acc[mt][nt], ah[mt], bh[nt]);
                    MMA16816(acc[mt][nt], ah[mt], bl[nt]);
                    MMA16816(acc[mt][nt], al[mt], bh[nt]);
                }
        }
        __syncthreads();
    }

    // epilogue: C writes (+ optional fused column stats)
#pragma unroll
    for (int mt = 0; mt < 2; mt++) {
        int row = bm + wm * 32 + mt * 16 + (lane >> 2);
#pragma unroll
        for (int nt = 0; nt < 8; nt++) {
            int col = bn + wn * 64 + nt * 8 + (lane & 3) * 2;
            float2 v0 = { acc[mt][nt][0], acc[mt][nt][1] };
            float2 v1 = { acc[mt][nt][2], acc[mt][nt][3] };
            *(float2*)(C + (size_t)row * ldc + col) = v0;
            *(float2*)(C + (size_t)(row + 8) * ldc + col) = v1;
        }
    }
    if (gsum) {
#pragma unroll
        for (int nt = 0; nt < 8; nt++) {
            float se = 0.f, so = 0.f, qe = 0.f, qo = 0.f;
#pragma unroll
            for (int mt = 0; mt < 2; mt++) {
                float e0 = acc[mt][nt][0], e1 = acc[mt][nt][1];
                float e2 = acc[mt][nt][2], e3 = acc[mt][nt][3];
                se += e0 + e2; so += e1 + e3;
                qe += e0 * e0 + e2 * e2; qo += e1 * e1 + e3 * e3;
            }
#pragma unroll
            for (int off = 4; off < 32; off <<= 1) {
                se += __shfl_xor_sync(0xFFFFFFFFu, se, off);
                so += __shfl_xor_sync(0xFFFFFFFFu, so, off);
                qe += __shfl_xor_sync(0xFFFFFFFFu, qe, off);
                qo += __shfl_xor_sync(0xFFFFFFFFu, qo, off);
            }
            if (lane < 4) {
                int cl = wn * 64 + nt * 8 + lane * 2;
                atomicAdd(&s_sum[cl], se);     atomicAdd(&s_sum[cl + 1], so);
                atomicAdd(&s_ss[cl], qe);      atomicAdd(&s_ss[cl + 1], qo);
            }
        }
        __syncthreads();
        if (tid < 128) {
            atomicAdd(&gsum[bn + tid], s_sum[tid]);
            atomicAdd(&gss[bn + tid], s_ss[tid]);
        }
    }
}

// ================= small elementwise / stats kernels ============================
__global__ void lin1_kernel(const float* __restrict__ xyz, const float* __restrict__ W1,
                            float* __restrict__ out) {
    int t = blockIdx.x * blockDim.x + threadIdx.x;
    int r = t >> 6, o = t & 63;
    float x0 = xyz[r * 3 + 0], x1 = xyz[r * 3 + 1], x2 = xyz[r * 3 + 2];
    out[t] = x0 * W1[o * 3 + 0] + x1 * W1[o * 3 + 1] + x2 * W1[o * 3 + 2];
}

__global__ void zero_stats_kernel(float* __restrict__ s, float* __restrict__ q) {
    int t = blockIdx.x * blockDim.x + threadIdx.x;
    if (t < 1024) { s[t] = 0.f; q[t] = 0.f; }
}

__global__ void colstats_kernel(const float* __restrict__ x, int M, int C,
                                float* __restrict__ sum, float* __restrict__ ss) {
    int c = blockIdx.y * blockDim.x + threadIdx.x;
    if (c >= C) return;
    size_t r0 = (size_t)blockIdx.x * 512;
    const float* p = x + r0 * C + c;
    float s = 0.f, q = 0.f;
    for (int r = 0; r < 512; r++) { float v = p[(size_t)r * C]; s += v; q += v * v; }
    atomicAdd(&sum[c], s);
    atomicAdd(&ss[c], q);
}

__device__ __forceinline__ uint32_t pk_h2(float a, float b) {
    __half2 t = __floats2half2_rn(a, b);
    return *(uint32_t*)&t;
}

// BN + ReLU + hi/lo fp16 split (reads fp32 once, writes fp16 pair)
__global__ void bnrelu_split_kernel(const float* __restrict__ x,
                                    const float* __restrict__ sum, const float* __restrict__ ss,
                                    const float* __restrict__ g, const float* __restrict__ bta,
                                    __half* __restrict__ hi, __half* __restrict__ lo,
                                    int M, int C) {
    int t = blockIdx.x * blockDim.x + threadIdx.x;
    int C4 = C >> 2;
    if (t >= M * C4) return;
    int c = (t % C4) << 2;
    float invM = 1.0f / (float)M;
    float4 v = ((const float4*)x)[t];
    float o[4];
    float vv[4] = { v.x, v.y, v.z, v.w };
#pragma unroll
    for (int i = 0; i < 4; i++) {
        float m = sum[c + i] * invM;
        float var = ss[c + i] * invM - m * m;
        float sc = g[c + i] * rsqrtf(var + BN_EPS);
        o[i] = fmaxf((vv[i] - m) * sc + bta[c + i], 0.f);
    }
    float h[4];
#pragma unroll
    for (int i = 0; i < 4; i++) h[i] = __half2float(__float2half_rn(o[i]));
    uint2 H = { pk_h2(o[0], o[1]), pk_h2(o[2], o[3]) };
    uint2 L = { pk_h2(o[0] - h[0], o[1] - h[1]), pk_h2(o[2] - h[2], o[3] - h[3]) };
    ((uint2*)hi)[t] = H;
    ((uint2*)lo)[t] = L;
}

// plain hi/lo split (weights, l0)
__global__ void split_kernel(const float* __restrict__ x,
                             __half* __restrict__ hi, __half* __restrict__ lo, int n4) {
    int t = blockIdx.x * blockDim.x + threadIdx.x;
    if (t >= n4) return;
    float4 v = ((const float4*)x)[t];
    float o[4] = { v.x, v.y, v.z, v.w };
    float h[4];
#pragma unroll
    for (int i = 0; i < 4; i++) h[i] = __half2float(__float2half_rn(o[i]));
    uint2 H = { pk_h2(o[0], o[1]), pk_h2(o[2], o[3]) };
    uint2 L = { pk_h2(o[0] - h[0], o[1] - h[1]), pk_h2(o[2] - h[2], o[3] - h[3]) };
    ((uint2*)hi)[t] = H;
    ((uint2*)lo)[t] = L;
}

// kNN: k=8 smallest (stable ties, matches top_k(-d2))
__global__ void knn_kernel(const float* __restrict__ xyz, int* __restrict__ idx) {
    __shared__ float sx[1024], sy[1024], sz[1024], sq[1024];
    int b = blockIdx.y, tid = threadIdx.x;
    for (int i = tid; i < 1024; i += 256) {
        float x = xyz[((b << 10) + i) * 3 + 0];
        float y = xyz[((b << 10) + i) * 3 + 1];
        float z = xyz[((b << 10) + i) * 3 + 2];
        sx[i] = x; sy[i] = y; sz[i] = z;
        sq[i] = x * x + y * y + z * z;
    }
    __syncthreads();
    int n = blockIdx.x * 256 + tid;
    float qx = sx[n], qy = sy[n], qz = sz[n], qs = sq[n];
    float bd[8]; int bi[8];
#pragma unroll
    for (int j = 0; j < 8; j++) { bd[j] = 3.4e38f; bi[j] = 0; }
    for (int m = 0; m < 1024; m++) {
        float d2 = qs + sq[m] - 2.f * (qx * sx[m] + qy * sy[m] + qz * sz[m]);
        if (d2 < bd[7]) {
            bd[7] = d2; bi[7] = m;
#pragma unroll
            for (int j = 7; j > 0; j--) {
                if (bd[j] < bd[j - 1]) {
                    float td = bd[j]; bd[j] = bd[j - 1]; bd[j - 1] = td;
                    int ti = bi[j]; bi[j] = bi[j - 1]; bi[j - 1] = ti;
                }
            }
        }
    }
#pragma unroll
    for (int j = 0; j < 8; j++) idx[((b << 10) + n) * 8 + j] = bi[j];
}

// expand (Q[idx]-Q[c]+R[c]) with fused column stats.
// grid: (65536/256, C4/128), block 128. thread owns 4 columns across 256 rows.
__global__ void expand_stats_kernel(const float4* __restrict__ Q, const float4* __restrict__ R,
                                    const int* __restrict__ idx, float4* __restrict__ out,
                                    int C4, float* __restrict__ gsum, float* __restrict__ gss) {
    __shared__ int sidx[256];
    int c4 = blockIdx.y * 128 + threadIdx.x;
    int r0 = blockIdx.x * 256;
    for (int i = threadIdx.x; i < 256; i += 128) sidx[i] = idx[r0 + i];
    __syncthreads();
    float s0 = 0.f, s1 = 0.f, s2 = 0.f, s3 = 0.f;
    float q0 = 0.f, q1 = 0.f, q2 = 0.f, q3 = 0.f;
    for (int r = 0; r < 256; r++) {
        int row = r0 + r;
        int bn = row >> 3;
        int b = bn >> 10;
        int src = (b << 10) + sidx[r];
        float4 qa = Q[(size_t)src * C4 + c4];
        float4 qc = Q[(size_t)bn * C4 + c4];
        float4 rr = R[(size_t)bn * C4 + c4];
        float4 o;
        o.x = qa.x - qc.x + rr.x;
        o.y = qa.y - qc.y + rr.y;
        o.z = qa.z - qc.z + rr.z;
        o.w = qa.w - qc.w + rr.w;
        out[(size_t)row * C4 + c4] = o;
        s0 += o.x; s1 += o.y; s2 += o.z; s3 += o.w;
        q0 += o.x * o.x; q1 += o.y * o.y; q2 += o.z * o.z; q3 += o.w * o.w;
    }
    int c = c4 << 2;
    atomicAdd(&gsum[c + 0], s0); atomicAdd(&gsum[c + 1], s1);
    atomicAdd(&gsum[c + 2], s2); atomicAdd(&gsum[c + 3], s3);
    atomicAdd(&gss[c + 0], q0); atomicAdd(&gss[c + 1], q1);
    atomicAdd(&gss[c + 2], q2); atomicAdd(&gss[c + 3], q3);
}

// BN + ReLU + max over k=8 (row-major output, for l0)
__global__ void bn_relu_max_kernel(const float* __restrict__ x,
                                   const float* __restrict__ sum, const float* __restrict__ ss,
                                   const float* __restrict__ g, const float* __restrict__ bta,
                                   float* __restrict__ out, int C) {
    int t = blockIdx.x * blockDim.x + threadIdx.x;
    if (t >= 8192 * C) return;
    int c = t % C;
    int bn = t / C;
    const float invM = 1.0f / 65536.0f;
    float m = sum[c] * invM;
    float var = ss[c] * invM - m * m;
    float sc = g[c] * rsqrtf(var + BN_EPS);
    float bb = bta[c];
    const float* p = x + (size_t)bn * 8 * C + c;
    float best = -3.4e38f;
#pragma unroll
    for (int k = 0; k < 8; k++) best = fmaxf(best, (p[(size_t)k * C] - m) * sc + bb);
    out[t] = fmaxf(best, 0.f);
}

// BN + ReLU + max over k=8 + transpose (B,C,N), smem-tiled coalesced writes
// grid: (1024/32, C/32, 8), block (32,8)
__global__ void bn_relu_max_t_kernel(const float* __restrict__ x,
                                     const float* __restrict__ sum, const float* __restrict__ ss,
                                     const float* __restrict__ g, const float* __restrict__ bta,
                                     float* __restrict__ out, int C) {
    __shared__ float tile[32][33];
    int b = blockIdx.z;
    int n0 = blockIdx.x * 32;
    int c0 = blockIdx.y * 32;
    int c = c0 + threadIdx.x;
    const float invM = 1.0f / 65536.0f;
    float m = sum[c] * invM;
    float var = ss[c] * invM - m * m;
    float sc = g[c] * rsqrtf(var + BN_EPS);
    float bb = bta[c];
#pragma unroll
    for (int j = 0; j < 4; j++) {
        int nl = threadIdx.y + j * 8;
        int bn = (b << 10) + n0 + nl;
        const float* p = x + (size_t)bn * 8 * C + c;
        float best = -3.4e38f;
#pragma unroll
        for (int k = 0; k < 8; k++) best = fmaxf(best, (p[(size_t)k * C] - m) * sc + bb);
        tile[threadIdx.x][nl] = fmaxf(best, 0.f);
    }
    __syncthreads();
#pragma unroll
    for (int j = 0; j < 4; j++) {
        int cl = threadIdx.y + j * 8;
        out[((size_t)b * C + c0 + cl) * 1024 + n0 + threadIdx.x] = tile[cl][threadIdx.x];
    }
}

// ================= host orchestration ===========================================
extern "C" void kernel_launch(void* const* d_in, const int* in_sizes, int n_in,
                              void* d_out, int out_size) {
    const float* xyz = (const float*)d_in[0];
    const float* W1  = (const float*)d_in[1];
    const float* g1  = (const float*)d_in[2];
    const float* b1  = (const float*)d_in[3];
    const float* W2  = (const float*)d_in[4];
    const float* g2  = (const float*)d_in[5];
    const float* b2  = (const float*)d_in[6];
    const float* WA1 = (const float*)d_in[7];
    const float* gA1 = (const float*)d_in[8];
    const float* bA1 = (const float*)d_in[9];
    const float* WA2 = (const float*)d_in[10];
    const float* gA2 = (const float*)d_in[11];
    const float* bA2 = (const float*)d_in[12];
    const float* WB1 = (const float*)d_in[13];
    const float* gB1 = (const float*)d_in[14];
    const float* bB1 = (const float*)d_in[15];
    const float* WB2 = (const float*)d_in[16];
    const float* gB2 = (const float*)d_in[17];
    const float* bB2 = (const float*)d_in[18];
    float* out = (float*)d_out;

    float *h1, *h2, *Q, *R, *l0, *big, *sumb, *ssb;
    __half *h1h, *h1l, *h2h, *h2l, *l0h, *l0l, *Ah, *Al;
    __half *W2h, *W2l, *WA1h, *WA1l, *WA2h, *WA2l, *WB1h, *WB1l, *WB2h, *WB2l;
    int* idx;
    cudaGetSymbolAddress((void**)&h1, d_h1);   cudaGetSymbolAddress((void**)&h1h, d_h1h);
    cudaGetSymbolAddress((void**)&h1l, d_h1l); cudaGetSymbolAddress((void**)&h2, d_h2);
    cudaGetSymbolAddress((void**)&h2h, d_h2h); cudaGetSymbolAddress((void**)&h2l, d_h2l);
    cudaGetSymbolAddress((void**)&idx, d_idx); cudaGetSymbolAddress((void**)&Q, d_Q);
    cudaGetSymbolAddress((void**)&R, d_R);     cudaGetSymbolAddress((void**)&l0, d_l0);
    cudaGetSymbolAddress((void**)&l0h, d_l0h); cudaGetSymbolAddress((void**)&l0l, d_l0l);
    cudaGetSymbolAddress((void**)&big, d_big); cudaGetSymbolAddress((void**)&Ah, d_Ah);
    cudaGetSymbolAddress((void**)&Al, d_Al);
    cudaGetSymbolAddress((void**)&W2h, d_W2h);   cudaGetSymbolAddress((void**)&W2l, d_W2l);
    cudaGetSymbolAddress((void**)&WA1h, d_WA1h); cudaGetSymbolAddress((void**)&WA1l, d_WA1l);
    cudaGetSymbolAddress((void**)&WA2h, d_WA2h); cudaGetSymbolAddress((void**)&WA2l, d_WA2l);
    cudaGetSymbolAddress((void**)&WB1h, d_WB1h); cudaGetSymbolAddress((void**)&WB1l, d_WB1l);
    cudaGetSymbolAddress((void**)&WB2h, d_WB2h); cudaGetSymbolAddress((void**)&WB2l, d_WB2l);
    cudaGetSymbolAddress((void**)&sumb, d_sum);  cudaGetSymbolAddress((void**)&ssb, d_ss);

    cudaFuncSetAttribute(gemm_hmma_kernel, cudaFuncAttributeMaxDynamicSharedMemorySize,
                         GSMEM_DYN);
    const int T = 256;

    // weight splits
    split_kernel<<<16, T>>>(W2, W2h, W2l, 256 * 64 / 4);
    split_kernel<<<256, T>>>(WA1, WA1h, WA1l, 512 * 512 / 4);
    split_kernel<<<256, T>>>(WA2, WA2h, WA2l, 512 * 512 / 4);
    split_kernel<<<1024, T>>>(WB1, WB1h, WB1l, 1024 * 1024 / 4);
    split_kernel<<<1024, T>>>(WB2, WB2h, WB2l, 1024 * 1024 / 4);

    // kNN
    knn_kernel<<<dim3(4, 8), T>>>(xyz, idx);

    // layer 1: h1 = bn_relu(xyz @ W1^T), split
    lin1_kernel<<<2048, T>>>(xyz, W1, h1);
    zero_stats_kernel<<<4, T>>>(sumb, ssb);
    colstats_kernel<<<dim3(16, 1), T>>>(h1, 8192, 64, sumb, ssb);
    bnrelu_split_kernel<<<512, T>>>(h1, sumb, ssb, g1, b1, h1h, h1l, 8192, 64);

    // layer 2: h2 = h1 @ W2^T (+stats), bn_relu split
    zero_stats_kernel<<<4, T>>>(sumb, ssb);
    gemm_hmma_kernel<<<dim3(2, 64), T, GSMEM_DYN>>>(h1h, h1l, 64, W2h, W2l, 64,
                                                    h2, 256, 64, sumb, ssb);
    bnrelu_split_kernel<<<2048, T>>>(h2, sumb, ssb, g2, b2, h2h, h2l, 8192, 256);

    // ---- local_op A ----
    gemm_hmma_kernel<<<dim3(4, 64), T, GSMEM_DYN>>>(h2h, h2l, 256, WA1h, WA1l, 512,
                                                    Q, 512, 256, nullptr, nullptr);
    gemm_hmma_kernel<<<dim3(4, 64), T, GSMEM_DYN>>>(h2h, h2l, 256, WA1h + 256, WA1l + 256, 512,
                                                    R, 512, 256, nullptr, nullptr);
    zero_stats_kernel<<<4, T>>>(sumb, ssb);
    expand_stats_kernel<<<dim3(256, 1), 128>>>((const float4*)Q, (const float4*)R, idx,
                                               (float4*)big, 128, sumb, ssb);
    bnrelu_split_kernel<<<32768, T>>>(big, sumb, ssb, gA1, bA1, Ah, Al, 65536, 512);
    zero_stats_kernel<<<4, T>>>(sumb, ssb);
    gemm_hmma_kernel<<<dim3(4, 512), T, GSMEM_DYN>>>(Ah, Al, 512, WA2h, WA2l, 512,
                                                     big, 512, 512, sumb, ssb);
    bn_relu_max_kernel<<<16384, T>>>(big, sumb, ssb, gA2, bA2, l0, 512);
    split_kernel<<<4096, T>>>(l0, l0h, l0l, 8192 * 512 / 4);

    // ---- local_op B ----
    gemm_hmma_kernel<<<dim3(8, 64), T, GSMEM_DYN>>>(l0h, l0l, 512, WB1h, WB1l, 1024,
                                                    Q, 1024, 512, nullptr, nullptr);
    gemm_hmma_kernel<<<dim3(8, 64), T, GSMEM_DYN>>>(l0h, l0l, 512, WB1h + 512, WB1l + 512, 1024,
                                                    R, 1024, 512, nullptr, nullptr);
    zero_stats_kernel<<<4, T>>>(sumb, ssb);
    expand_stats_kernel<<<dim3(256, 2), 128>>>((const float4*)Q, (const float4*)R, idx,
                                               (float4*)big, 256, sumb, ssb);
    bnrelu_split_kernel<<<65536, T>>>(big, sumb, ssb, gB1, bB1, Ah, Al, 65536, 1024);
    zero_stats_kernel<<<4, T>>>(sumb, ssb);
    gemm_hmma_kernel<<<dim3(8, 512), T, GSMEM_DYN>>>(Ah, Al, 1024, WB2h, WB2l, 1024,
                                                     big, 1024, 1024, sumb, ssb);
    bn_relu_max_t_kernel<<<dim3(32, 32, 8), dim3(32, 8)>>>(big, sumb, ssb, gB2, bB2, out, 1024);
}

// round 5
// speedup vs baseline: 2.1862x; 1.1137x over previous
#include <cuda_runtime.h>
#include <cuda_fp16.h>
#include <cstdint>

#define BN_EPS 1e-5f

// ================= persistent scratch (device globals; no allocations) ==========
__device__ float d_h1[8192 * 64];
__device__ __half d_h1h[8192 * 64], d_h1l[8192 * 64];
__device__ float d_h2[8192 * 256];
__device__ __half d_h2h[8192 * 256], d_h2l[8192 * 256];
__device__ __half d_l0h[8192 * 512], d_l0l[8192 * 512];   // l0 fp16 pair (8 MB each)
__device__ int   d_idx[8192 * 8];
__device__ float d_Q[8192 * 1024];
__device__ float d_R[8192 * 1024];
__device__ float d_mx[8192 * 1024];                   // raw max-over-k scratch (33 MB)
__device__ __half d_Ah[65536 * 1024];                 // 128 MB fp16 hi (expanded)
__device__ __half d_Al[65536 * 1024];                 // 128 MB fp16 lo (expanded)
__device__ __half d_W2h[256 * 64],     d_W2l[256 * 64];
__device__ __half d_WA1h[512 * 512],   d_WA1l[512 * 512];
__device__ __half d_WA2h[512 * 512],   d_WA2l[512 * 512];
__device__ __half d_WB1h[1024 * 1024], d_WB1l[1024 * 1024];
__device__ __half d_WB2h[1024 * 1024], d_WB2l[1024 * 1024];
__device__ float d_sum[1024];
__device__ float d_ss[1024];

// ================= PTX helpers (arch-neutral, sm_80+) ===========================
__device__ __forceinline__ uint32_t smem_u32(const void* p) {
    uint32_t a;
    asm("{ .reg .u64 t; cvta.to.shared.u64 t, %1; cvt.u32.u64 %0, t; }" : "=r"(a) : "l"(p));
    return a;
}
__device__ __forceinline__ void cpa16(uint32_t s, const void* g) {
    asm volatile("cp.async.cg.shared.global [%0], [%1], 16;" :: "r"(s), "l"(g));
}
#define CP_COMMIT() asm volatile("cp.async.commit_group;" ::: "memory")
#define CP_WAIT0()  asm volatile("cp.async.wait_group 0;" ::: "memory")
#define CP_WAIT1()  asm volatile("cp.async.wait_group 1;" ::: "memory")

#define LDSM4(r0, r1, r2, r3, a) \
    asm volatile("ldmatrix.sync.aligned.m8n8.x4.shared.b16 {%0,%1,%2,%3}, [%4];" \
                 : "=r"(r0), "=r"(r1), "=r"(r2), "=r"(r3) : "r"(a))

#define MMA16816(c, a, b) \
    asm volatile("mma.sync.aligned.m16n8k16.row.col.f32.f16.f16.f32 " \
                 "{%0,%1,%2,%3}, {%4,%5,%6,%7}, {%8,%9}, {%0,%1,%2,%3};" \
                 : "+f"((c)[0]), "+f"((c)[1]), "+f"((c)[2]), "+f"((c)[3]) \
                 : "r"((a)[0]), "r"((a)[1]), "r"((a)[2]), "r"((a)[3]), \
                   "r"((b)[0]), "r"((b)[1]))

// ================= HMMA split-fp16 GEMM =========================================
// C[M,N](fp32) = (Ah+Al)[M,K] @ (Bh+Bl)[N,K]^T  via 3 fp16 products (AlBl dropped).
// CTA tile 128x128, BK=32, 3-stage cp.async pipeline, 8 warps of 32(m)x64(n).
// Smem rows padded to 40 halves (80B) -> ldmatrix conflict-free.
// Modes: maxout != nullptr -> fused raw max over k=8 groups (no C write) + stats.
//        else C write, optional fused stats.
#define GBK 32
#define GMT_B 10240                   // bytes per matrix tile (128 * 80)
#define GSTAGE 40960                  // Ah|Al|Bh|Bl
#define GSMEM_DYN 122880              // 3 stages

__device__ __forceinline__ void g_load_stage(uint32_t st,
        const __half* __restrict__ Ah, const __half* __restrict__ Al, int lda,
        const __half* __restrict__ Bh, const __half* __restrict__ Bl, int ldb,
        int bm, int bn, int kc, int r0, int r1, int cg,
        uint32_t so0, uint32_t so1) {
    size_t ga0 = (size_t)(bm + r0) * lda + kc + cg * 8;
    size_t ga1 = (size_t)(bm + r1) * lda + kc + cg * 8;
    size_t gb0 = (size_t)(bn + r0) * ldb + kc + cg * 8;
    size_t gb1 = (size_t)(bn + r1) * ldb + kc + cg * 8;
    cpa16(st + so0, Ah + ga0);               cpa16(st + so1, Ah + ga1);
    cpa16(st + GMT_B + so0, Al + ga0);       cpa16(st + GMT_B + so1, Al + ga1);
    cpa16(st + 2 * GMT_B + so0, Bh + gb0);   cpa16(st + 2 * GMT_B + so1, Bh + gb1);
    cpa16(st + 3 * GMT_B + so0, Bl + gb0);   cpa16(st + 3 * GMT_B + so1, Bl + gb1);
}

__global__ void __launch_bounds__(256, 1)
gemm_hmma_kernel(const __half* __restrict__ Ah, const __half* __restrict__ Al, int lda,
                 const __half* __restrict__ Bh, const __half* __restrict__ Bl, int ldb,
                 float* __restrict__ C, float* __restrict__ maxout, int ldc, int K,
                 float* __restrict__ gsum, float* __restrict__ gss) {
    extern __shared__ char smem[];
    __shared__ float s_sum[128], s_ss[128];
    const int tid = threadIdx.x;
    const int lane = tid & 31, wid = tid >> 5;
    const int wm = wid & 3, wn = wid >> 2;           // 4 x 2 warp grid
    const int bm = blockIdx.y * 128, bn = blockIdx.x * 128;
    const uint32_t sb = smem_u32(smem);

    if (gsum && tid < 128) { s_sum[tid] = 0.f; s_ss[tid] = 0.f; }

    float acc[2][8][4];
#pragma unroll
    for (int i = 0; i < 2; i++)
#pragma unroll
        for (int j = 0; j < 8; j++)
#pragma unroll
            for (int v = 0; v < 4; v++) acc[i][j][v] = 0.f;

    // cp.async mapping: per matrix 512 x 16B chunks, 2 per thread
    const int r0 = tid >> 2, cg = tid & 3;
    const int r1 = (tid + 256) >> 2;
    const uint32_t so0 = (uint32_t)(r0 * 80 + cg * 16);
    const uint32_t so1 = (uint32_t)(r1 * 80 + cg * 16);

    // ldmatrix base addresses
    const uint32_t a_off = (uint32_t)((wm * 32 + (lane & 15)) * 80 + (lane >> 4) * 16);
    const int b_n = wn * 64 + (lane & 7) + ((lane >> 4) << 3);
    const uint32_t b_koff = (uint32_t)(((lane >> 3) & 1) * 16);

    const int NC = K / GBK;

    g_load_stage(sb, Ah, Al, lda, Bh, Bl, ldb, bm, bn, 0, r0, r1, cg, so0, so1);
    CP_COMMIT();
    g_load_stage(sb + GSTAGE, Ah, Al, lda, Bh, Bl, ldb, bm, bn, GBK, r0, r1, cg, so0, so1);
    CP_COMMIT();

    for (int c = 0; c < NC; c++) {
        if (c + 1 < NC) CP_WAIT1(); else CP_WAIT0();
        __syncthreads();
        if (c + 2 < NC) {
            g_load_stage(sb + (uint32_t)((c + 2) % 3) * GSTAGE, Ah, Al, lda, Bh, Bl, ldb,
                         bm, bn, (c + 2) * GBK, r0, r1, cg, so0, so1);
            CP_COMMIT();
        }
        uint32_t st = sb + (uint32_t)(c % 3) * GSTAGE;
#pragma unroll
        for (int kk = 0; kk < 2; kk++) {              // two k16 steps in BK=32
            uint32_t kb = (uint32_t)(kk * 32);        // bytes
            uint32_t ah[2][4], al[2][4], bh[8][2], bl[8][2];
#pragma unroll
            for (int mt = 0; mt < 2; mt++) {
                uint32_t aa = st + a_off + (uint32_t)(mt * 16 * 80) + kb;
                LDSM4(ah[mt][0], ah[mt][1], ah[mt][2], ah[mt][3], aa);
                LDSM4(al[mt][0], al[mt][1], al[mt][2], al[mt][3], aa + GMT_B);
            }
#pragma unroll
            for (int p = 0; p < 4; p++) {
                uint32_t ba = st + 2 * GMT_B +
                              (uint32_t)((b_n + p * 16) * 80) + b_koff + kb;
                LDSM4(bh[2 * p][0], bh[2 * p][1], bh[2 * p + 1][0], bh[2 * p + 1][1], ba);
                LDSM4(bl[2 * p][0], bl[2 * p][1], bl[2 * p + 1][0], bl[2 * p + 1][1],
                      ba + GMT_B);
            }
#pragma unroll
            for (int mt = 0; mt < 2; mt++)
#pragma unroll
                for (int nt = 0; nt < 8; nt++) {
                    MMA16816(acc[mt][nt], ah[mt], bh[nt]);
                    MMA16816(acc[mt][nt], ah[mt], bl[nt]);
                    MMA16816(acc[mt][nt], al[mt], bh[nt]);
                }
        }
    }

    // ---------------- epilogue -------------------------------------------------
    if (maxout) {
        // fused raw max over k=8 groups (each 8-row group lives in one mt quadrant:
        // rows r = lane>>2 (0..7) and r+8; group g = 16*mt tile rows / 8)
#pragma unroll
        for (int mt = 0; mt < 2; mt++) {
            int gA = (bm + wm * 32 + mt * 16) >> 3;   // output group rows gA, gA+1
#pragma unroll
            for (int nt = 0; nt < 8; nt++) {
                float m0 = acc[mt][nt][0], m1 = acc[mt][nt][1];
                float m2 = acc[mt][nt][2], m3 = acc[mt][nt][3];
#pragma unroll
                for (int off = 4; off < 32; off <<= 1) {
                    m0 = fmaxf(m0, __shfl_xor_sync(0xFFFFFFFFu, m0, off));
                    m1 = fmaxf(m1, __shfl_xor_sync(0xFFFFFFFFu, m1, off));
                    m2 = fmaxf(m2, __shfl_xor_sync(0xFFFFFFFFu, m2, off));
                    m3 = fmaxf(m3, __shfl_xor_sync(0xFFFFFFFFu, m3, off));
                }
                if (lane < 4) {
                    int col = bn + wn * 64 + nt * 8 + lane * 2;
                    float2 v0 = { m0, m1 }, v1 = { m2, m3 };
                    *(float2*)(maxout + (size_t)gA * ldc + col) = v0;
                    *(float2*)(maxout + (size_t)(gA + 1) * ldc + col) = v1;
                }
            }
        }
    } else {
#pragma unroll
        for (int mt = 0; mt < 2; mt++) {
            int row = bm + wm * 32 + mt * 16 + (lane >> 2);
#pragma unroll
            for (int nt = 0; nt < 8; nt++) {
                int col = bn + wn * 64 + nt * 8 + (lane & 3) * 2;
                float2 v0 = { acc[mt][nt][0], acc[mt][nt][1] };
                float2 v1 = { acc[mt][nt][2], acc[mt][nt][3] };
                *(float2*)(C + (size_t)row * ldc + col) = v0;
                *(float2*)(C + (size_t)(row + 8) * ldc + col) = v1;
            }
        }
    }
    if (gsum) {
#pragma unroll
        for (int nt = 0; nt < 8; nt++) {
            float se = 0.f, so = 0.f, qe = 0.f, qo = 0.f;
#pragma unroll
            for (int mt = 0; mt < 2; mt++) {
                float e0 = acc[mt][nt][0], e1 = acc[mt][nt][1];
                float e2 = acc[mt][nt][2], e3 = acc[mt][nt][3];
                se += e0 + e2; so += e1 + e3;
                qe += e0 * e0 + e2 * e2; qo += e1 * e1 + e3 * e3;
            }
#pragma unroll
            for (int off = 4; off < 32; off <<= 1) {
                se += __shfl_xor_sync(0xFFFFFFFFu, se, off);
                so += __shfl_xor_sync(0xFFFFFFFFu, so, off);
                qe += __shfl_xor_sync(0xFFFFFFFFu, qe, off);
                qo += __shfl_xor_sync(0xFFFFFFFFu, qo, off);
            }
            if (lane < 4) {
                int cl = wn * 64 + nt * 8 + lane * 2;
                atomicAdd(&s_sum[cl], se);     atomicAdd(&s_sum[cl + 1], so);
                atomicAdd(&s_ss[cl], qe);      atomicAdd(&s_ss[cl + 1], qo);
            }
        }
        __syncthreads();
        if (tid < 128) {
            atomicAdd(&gsum[bn + tid], s_sum[tid]);
            atomicAdd(&gss[bn + tid], s_ss[tid]);
        }
    }
}

// ================= small elementwise / stats kernels ============================
__global__ void lin1_kernel(const float* __restrict__ xyz, const float* __restrict__ W1,
                            float* __restrict__ out) {
    int t = blockIdx.x * blockDim.x + threadIdx.x;
    int r = t >> 6, o = t & 63;
    float x0 = xyz[r * 3 + 0], x1 = xyz[r * 3 + 1], x2 = xyz[r * 3 + 2];
    out[t] = x0 * W1[o * 3 + 0] + x1 * W1[o * 3 + 1] + x2 * W1[o * 3 + 2];
}

__global__ void zero_stats_kernel(float* __restrict__ s, float* __restrict__ q) {
    int t = blockIdx.x * blockDim.x + threadIdx.x;
    if (t < 1024) { s[t] = 0.f; q[t] = 0.f; }
}

__global__ void colstats_kernel(const float* __restrict__ x, int M, int C,
                                float* __restrict__ sum, float* __restrict__ ss) {
    int c = blockIdx.y * blockDim.x + threadIdx.x;
    if (c >= C) return;
    size_t r0 = (size_t)blockIdx.x * 512;
    const float* p = x + r0 * C + c;
    float s = 0.f, q = 0.f;
    for (int r = 0; r < 512; r++) { float v = p[(size_t)r * C]; s += v; q += v * v; }
    atomicAdd(&sum[c], s);
    atomicAdd(&ss[c], q);
}

__device__ __forceinline__ uint32_t pk_h2(float a, float b) {
    __half2 t = __floats2half2_rn(a, b);
    return *(uint32_t*)&t;
}

// BN + ReLU + hi/lo fp16 split (reads fp32 once, writes fp16 pair).
__global__ void bnrelu_split_kernel(const float* __restrict__ x,
                                    const float* __restrict__ sum, const float* __restrict__ ss,
                                    const float* __restrict__ g, const float* __restrict__ bta,
                                    __half* __restrict__ hi, __half* __restrict__ lo,
                                    int Mstat, int Mrows, int C) {
    int t = blockIdx.x * blockDim.x + threadIdx.x;
    int C4 = C >> 2;
    if (t >= Mrows * C4) return;
    int c = (t % C4) << 2;
    float invM = 1.0f / (float)Mstat;
    float4 v = ((const float4*)x)[t];
    float vv[4] = { v.x, v.y, v.z, v.w };
    float o[4];
#pragma unroll
    for (int i = 0; i < 4; i++) {
        float m = sum[c + i] * invM;
        float var = ss[c + i] * invM - m * m;
        float sc = g[c + i] * rsqrtf(var + BN_EPS);
        o[i] = fmaxf((vv[i] - m) * sc + bta[c + i], 0.f);
    }
    float h[4];
#pragma unroll
    for (int i = 0; i < 4; i++) h[i] = __half2float(__float2half_rn(o[i]));
    uint2 H = { pk_h2(o[0], o[1]), pk_h2(o[2], o[3]) };
    uint2 L = { pk_h2(o[0] - h[0], o[1] - h[1]), pk_h2(o[2] - h[2], o[3] - h[3]) };
    ((uint2*)hi)[t] = H;
    ((uint2*)lo)[t] = L;
}

// plain hi/lo split (weights)
__global__ void split_kernel(const float* __restrict__ x,
                             __half* __restrict__ hi, __half* __restrict__ lo, int n4) {
    int t = blockIdx.x * blockDim.x + threadIdx.x;
    if (t >= n4) return;
    float4 v = ((const float4*)x)[t];
    float o[4] = { v.x, v.y, v.z, v.w };
    float h[4];
#pragma unroll
    for (int i = 0; i < 4; i++) h[i] = __half2float(__float2half_rn(o[i]));
    uint2 H = { pk_h2(o[0], o[1]), pk_h2(o[2], o[3]) };
    uint2 L = { pk_h2(o[0] - h[0], o[1] - h[1]), pk_h2(o[2] - h[2], o[3] - h[3]) };
    ((uint2*)hi)[t] = H;
    ((uint2*)lo)[t] = L;
}

// kNN: k=8 smallest (stable ties, matches top_k(-d2))
__global__ void knn_kernel(const float* __restrict__ xyz, int* __restrict__ idx) {
    __shared__ float sx[1024], sy[1024], sz[1024], sq[1024];
    int b = blockIdx.y, tid = threadIdx.x;
    for (int i = tid; i < 1024; i += 256) {
        float x = xyz[((b << 10) + i) * 3 + 0];
        float y = xyz[((b << 10) + i) * 3 + 1];
        float z = xyz[((b << 10) + i) * 3 + 2];
        sx[i] = x; sy[i] = y; sz[i] = z;
        sq[i] = x * x + y * y + z * z;
    }
    __syncthreads();
    int n = blockIdx.x * 256 + tid;
    float qx = sx[n], qy = sy[n], qz = sz[n], qs = sq[n];
    float bd[8]; int bi[8];
#pragma unroll
    for (int j = 0; j < 8; j++) { bd[j] = 3.4e38f; bi[j] = 0; }
    for (int m = 0; m < 1024; m++) {
        float d2 = qs + sq[m] - 2.f * (qx * sx[m] + qy * sy[m] + qz * sz[m]);
        if (d2 < bd[7]) {
            bd[7] = d2; bi[7] = m;
#pragma unroll
            for (int j = 7; j > 0; j--) {
                if (bd[j] < bd[j - 1]) {
                    float td = bd[j]; bd[j] = bd[j - 1]; bd[j - 1] = td;
                    int ti = bi[j]; bi[j] = bi[j - 1]; bi[j - 1] = ti;
                }
            }
        }
    }
#pragma unroll
    for (int j = 0; j < 8; j++) idx[((b << 10) + n) * 8 + j] = bi[j];
}

// expand stats only (no materialization): o = Q[idx]-Qc+Rc, column sum/sumsq.
// grid: (65536/256, C4/128), block 128.
__global__ void expand_stats_kernel(const float4* __restrict__ Q, const float4* __restrict__ R,
                                    const int* __restrict__ idx, int C4,
                                    float* __restrict__ gsum, float* __restrict__ gss) {
    __shared__ int sidx[256];
    int c4 = blockIdx.y * 128 + threadIdx.x;
    int r0 = blockIdx.x * 256;
    for (int i = threadIdx.x; i < 256; i += 128) sidx[i] = idx[r0 + i];
    __syncthreads();
    int bn0 = r0 >> 3;
    int b = bn0 >> 10;
    float s[4] = {0.f, 0.f, 0.f, 0.f}, q[4] = {0.f, 0.f, 0.f, 0.f};
    for (int gg = 0; gg < 32; gg++) {
        int bn = bn0 + gg;
        float4 qc = Q[(size_t)bn * C4 + c4];
        float4 rr = R[(size_t)bn * C4 + c4];
        float bx = rr.x - qc.x, by = rr.y - qc.y, bz = rr.z - qc.z, bw = rr.w - qc.w;
#pragma unroll
        for (int k = 0; k < 8; k++) {
            int src = (b << 10) + sidx[gg * 8 + k];
            float4 qa = Q[(size_t)src * C4 + c4];
            float ox = qa.x + bx, oy = qa.y + by, oz = qa.z + bz, ow = qa.w + bw;
            s[0] += ox; s[1] += oy; s[2] += oz; s[3] += ow;
            q[0] += ox * ox; q[1] += oy * oy; q[2] += oz * oz; q[3] += ow * ow;
        }
    }
    int c = c4 << 2;
#pragma unroll
    for (int i = 0; i < 4; i++) { atomicAdd(&gsum[c + i], s[i]); atomicAdd(&gss[c + i], q[i]); }
}

// expand recompute + BN + ReLU + hi/lo fp16 split (writes only fp16 pairs).
__global__ void expand_bnrelu_split_kernel(
        const float4* __restrict__ Q, const float4* __restrict__ R,
        const int* __restrict__ idx, int C4,
        const float* __restrict__ sum, const float* __restrict__ ss,
        const float* __restrict__ g, const float* __restrict__ bta,
        __half* __restrict__ hi, __half* __restrict__ lo) {
    __shared__ int sidx[256];
    int c4 = blockIdx.y * 128 + threadIdx.x;
    int r0 = blockIdx.x * 256;
    for (int i = threadIdx.x; i < 256; i += 128) sidx[i] = idx[r0 + i];
    __syncthreads();
    int bn0 = r0 >> 3;
    int b = bn0 >> 10;
    const float invM = 1.0f / 65536.0f;
    int c = c4 << 2;
    float m[4], sc[4], bb[4];
#pragma unroll
    for (int i = 0; i < 4; i++) {
        m[i] = sum[c + i] * invM;
        float var = ss[c + i] * invM - m[i] * m[i];
        sc[i] = g[c + i] * rsqrtf(var + BN_EPS);
        bb[i] = bta[c + i];
    }
    for (int gg = 0; gg < 32; gg++) {
        int bn = bn0 + gg;
        float4 qc = Q[(size_t)bn * C4 + c4];
        float4 rr = R[(size_t)bn * C4 + c4];
        float bx = rr.x - qc.x, by = rr.y - qc.y, bz = rr.z - qc.z, bw = rr.w - qc.w;
#pragma unroll
        for (int k = 0; k < 8; k++) {
            int row = bn * 8 + k;
            int src = (b << 10) + sidx[gg * 8 + k];
            float4 qa = Q[(size_t)src * C4 + c4];
            float o[4] = { qa.x + bx, qa.y + by, qa.z + bz, qa.w + bw };
            float h[4];
#pragma unroll
            for (int i = 0; i < 4; i++) {
                o[i] = fmaxf((o[i] - m[i]) * sc[i] + bb[i], 0.f);
                h[i] = __half2float(__float2half_rn(o[i]));
            }
            uint2 H = { pk_h2(o[0], o[1]), pk_h2(o[2], o[3]) };
            uint2 L = { pk_h2(o[0] - h[0], o[1] - h[1]), pk_h2(o[2] - h[2], o[3] - h[3]) };
            ((uint2*)hi)[(size_t)row * C4 + c4] = H;
            ((uint2*)lo)[(size_t)row * C4 + c4] = L;
        }
    }
}

// finish: BN+ReLU of raw max (stats over 65536 raw rows) -> fp16 split (l0)
__global__ void finish_split_kernel(const float* __restrict__ mx,
                                    const float* __restrict__ sum, const float* __restrict__ ss,
                                    const float* __restrict__ g, const float* __restrict__ bta,
                                    __half* __restrict__ hi, __half* __restrict__ lo, int C) {
    int t = blockIdx.x * blockDim.x + threadIdx.x;
    int C4 = C >> 2;
    if (t >= 8192 * C4) return;
    int c = (t % C4) << 2;
    const float invM = 1.0f / 65536.0f;
    float4 v = ((const float4*)mx)[t];
    float vv[4] = { v.x, v.y, v.z, v.w };
    float o[4], h[4];
#pragma unroll
    for (int i = 0; i < 4; i++) {
        float m = sum[c + i] * invM;
        float var = ss[c + i] * invM - m * m;
        float sc = g[c + i] * rsqrtf(var + BN_EPS);
        o[i] = fmaxf((vv[i] - m) * sc + bta[c + i], 0.f);
        h[i] = __half2float(__float2half_rn(o[i]));
    }
    uint2 H = { pk_h2(o[0], o[1]), pk_h2(o[2], o[3]) };
    uint2 L = { pk_h2(o[0] - h[0], o[1] - h[1]), pk_h2(o[2] - h[2], o[3] - h[3]) };
    ((uint2*)hi)[t] = H;
    ((uint2*)lo)[t] = L;
}

// finish: BN+ReLU of raw max + transpose to (B, C, N). C=1024.
// grid (32, 32, 8), block (32,8)
__global__ void finish_out_t_kernel(const float* __restrict__ mx,
                                    const float* __restrict__ sum, const float* __restrict__ ss,
                                    const float* __restrict__ g, const float* __restrict__ bta,
                                    float* __restrict__ out) {
    __shared__ float tile[32][33];
    int b = blockIdx.z;
    int n0 = blockIdx.x * 32;
    int c0 = blockIdx.y * 32;
    int c = c0 + threadIdx.x;
    const float invM = 1.0f / 65536.0f;
    float m = sum[c] * invM;
    float var = ss[c] * invM - m * m;
    float sc = g[c] * rsqrtf(var + BN_EPS);
    float bb = bta[c];
#pragma unroll
    for (int j = 0; j < 4; j++) {
        int nl = threadIdx.y + j * 8;
        int bn = (b << 10) + n0 + nl;
        float v = mx[(size_t)bn * 1024 + c];
        tile[threadIdx.x][nl] = fmaxf((v - m) * sc + bb, 0.f);
    }
    __syncthreads();
#pragma unroll
    for (int j = 0; j < 4; j++) {
        int cl = threadIdx.y + j * 8;
        out[((size_t)b * 1024 + c0 + cl) * 1024 + n0 + threadIdx.x] = tile[cl][threadIdx.x];
    }
}

// ================= host orchestration ===========================================
extern "C" void kernel_launch(void* const* d_in, const int* in_sizes, int n_in,
                              void* d_out, int out_size) {
    const float* xyz = (const float*)d_in[0];
    const float* W1  = (const float*)d_in[1];
    const float* g1  = (const float*)d_in[2];
    const float* b1  = (const float*)d_in[3];
    const float* W2  = (const float*)d_in[4];
    const float* g2  = (const float*)d_in[5];
    const float* b2  = (const float*)d_in[6];
    const float* WA1 = (const float*)d_in[7];
    const float* gA1 = (const float*)d_in[8];
    const float* bA1 = (const float*)d_in[9];
    const float* WA2 = (const float*)d_in[10];
    const float* gA2 = (const float*)d_in[11];
    const float* bA2 = (const float*)d_in[12];
    const float* WB1 = (const float*)d_in[13];
    const float* gB1 = (const float*)d_in[14];
    const float* bB1 = (const float*)d_in[15];
    const float* WB2 = (const float*)d_in[16];
    const float* gB2 = (const float*)d_in[17];
    const float* bB2 = (const float*)d_in[18];
    float* out = (float*)d_out;

    float *h1, *h2, *Q, *R, *mx, *sumb, *ssb;
    __half *h1h, *h1l, *h2h, *h2l, *l0h, *l0l, *Ah, *Al;
    __half *W2h, *W2l, *WA1h, *WA1l, *WA2h, *WA2l, *WB1h, *WB1l, *WB2h, *WB2l;
    int* idx;
    cudaGetSymbolAddress((void**)&h1, d_h1);   cudaGetSymbolAddress((void**)&h1h, d_h1h);
    cudaGetSymbolAddress((void**)&h1l, d_h1l); cudaGetSymbolAddress((void**)&h2, d_h2);
    cudaGetSymbolAddress((void**)&h2h, d_h2h); cudaGetSymbolAddress((void**)&h2l, d_h2l);
    cudaGetSymbolAddress((void**)&l0h, d_l0h); cudaGetSymbolAddress((void**)&l0l, d_l0l);
    cudaGetSymbolAddress((void**)&idx, d_idx); cudaGetSymbolAddress((void**)&Q, d_Q);
    cudaGetSymbolAddress((void**)&R, d_R);     cudaGetSymbolAddress((void**)&mx, d_mx);
    cudaGetSymbolAddress((void**)&Ah, d_Ah);   cudaGetSymbolAddress((void**)&Al, d_Al);
    cudaGetSymbolAddress((void**)&W2h, d_W2h);   cudaGetSymbolAddress((void**)&W2l, d_W2l);
    cudaGetSymbolAddress((void**)&WA1h, d_WA1h); cudaGetSymbolAddress((void**)&WA1l, d_WA1l);
    cudaGetSymbolAddress((void**)&WA2h, d_WA2h); cudaGetSymbolAddress((void**)&WA2l, d_WA2l);
    cudaGetSymbolAddress((void**)&WB1h, d_WB1h); cudaGetSymbolAddress((void**)&WB1l, d_WB1l);
    cudaGetSymbolAddress((void**)&WB2h, d_WB2h); cudaGetSymbolAddress((void**)&WB2l, d_WB2l);
    cudaGetSymbolAddress((void**)&sumb, d_sum);  cudaGetSymbolAddress((void**)&ssb, d_ss);

    cudaFuncSetAttribute(gemm_hmma_kernel, cudaFuncAttributeMaxDynamicSharedMemorySize,
                         GSMEM_DYN);
    const int T = 256;

    // weight splits
    split_kernel<<<16, T>>>(W2, W2h, W2l, 256 * 64 / 4);
    split_kernel<<<256, T>>>(WA1, WA1h, WA1l, 512 * 512 / 4);
    split_kernel<<<256, T>>>(WA2, WA2h, WA2l, 512 * 512 / 4);
    split_kernel<<<1024, T>>>(WB1, WB1h, WB1l, 1024 * 1024 / 4);
    split_kernel<<<1024, T>>>(WB2, WB2h, WB2l, 1024 * 1024 / 4);

    // kNN
    knn_kernel<<<dim3(4, 8), T>>>(xyz, idx);

    // layer 1: h1 = bn_relu(xyz @ W1^T), split
    lin1_kernel<<<2048, T>>>(xyz, W1, h1);
    zero_stats_kernel<<<4, T>>>(sumb, ssb);
    colstats_kernel<<<dim3(16, 1), T>>>(h1, 8192, 64, sumb, ssb);
    bnrelu_split_kernel<<<512, T>>>(h1, sumb, ssb, g1, b1, h1h, h1l, 8192, 8192, 64);

    // layer 2: h2 = h1 @ W2^T (+stats), bn_relu split
    zero_stats_kernel<<<4, T>>>(sumb, ssb);
    gemm_hmma_kernel<<<dim3(2, 64), T, GSMEM_DYN>>>(h1h, h1l, 64, W2h, W2l, 64,
                                                    h2, nullptr, 256, 64, sumb, ssb);
    bnrelu_split_kernel<<<2048, T>>>(h2, sumb, ssb, g2, b2, h2h, h2l, 8192, 8192, 256);

    // ---- local_op A ----
    gemm_hmma_kernel<<<dim3(4, 64), T, GSMEM_DYN>>>(h2h, h2l, 256, WA1h, WA1l, 512,
                                                    Q, nullptr, 512, 256, nullptr, nullptr);
    gemm_hmma_kernel<<<dim3(4, 64), T, GSMEM_DYN>>>(h2h, h2l, 256, WA1h + 256, WA1l + 256, 512,
                                                    R, nullptr, 512, 256, nullptr, nullptr);
    zero_stats_kernel<<<4, T>>>(sumb, ssb);
    expand_stats_kernel<<<dim3(256, 1), 128>>>((const float4*)Q, (const float4*)R, idx,
                                               128, sumb, ssb);
    expand_bnrelu_split_kernel<<<dim3(256, 1), 128>>>((const float4*)Q, (const float4*)R, idx,
                                                      128, sumb, ssb, gA1, bA1, Ah, Al);
    zero_stats_kernel<<<4, T>>>(sumb, ssb);
    gemm_hmma_kernel<<<dim3(4, 512), T, GSMEM_DYN>>>(Ah, Al, 512, WA2h, WA2l, 512,
                                                     nullptr, mx, 512, 512, sumb, ssb);
    finish_split_kernel<<<4096, T>>>(mx, sumb, ssb, gA2, bA2, l0h, l0l, 512);

    // ---- local_op B ----
    gemm_hmma_kernel<<<dim3(8, 64), T, GSMEM_DYN>>>(l0h, l0l, 512, WB1h, WB1l, 1024,
                                                    Q, nullptr, 1024, 512, nullptr, nullptr);
    gemm_hmma_kernel<<<dim3(8, 64), T, GSMEM_DYN>>>(l0h, l0l, 512, WB1h + 512, WB1l + 512, 1024,
                                                    R, nullptr, 1024, 512, nullptr, nullptr);
    zero_stats_kernel<<<4, T>>>(sumb, ssb);
    expand_stats_kernel<<<dim3(256, 2), 128>>>((const float4*)Q, (const float4*)R, idx,
                                               256, sumb, ssb);
    expand_bnrelu_split_kernel<<<dim3(256, 2), 128>>>((const float4*)Q, (const float4*)R, idx,
                                                      256, sumb, ssb, gB1, bB1, Ah, Al);
    zero_stats_kernel<<<4, T>>>(sumb, ssb);
    gemm_hmma_kernel<<<dim3(8, 512), T, GSMEM_DYN>>>(Ah, Al, 1024, WB2h, WB2l, 1024,
                                                     nullptr, mx, 1024, 1024, sumb, ssb);
    finish_out_t_kernel<<<dim3(32, 32, 8), dim3(32, 8)>>>(mx, sumb, ssb, gB2, bB2, out);
}

// round 7
// speedup vs baseline: 2.4487x; 1.1201x over previous
#include <cuda_runtime.h>
#include <cuda_fp16.h>
#include <cstdint>

#define BN_EPS 1e-5f

// ================= persistent scratch (device globals; no allocations) ==========
__device__ float d_h1[8192 * 64];
__device__ __half d_h1h[8192 * 64], d_h1l[8192 * 64];
__device__ float d_h2[8192 * 256];
__device__ __half d_h2h[8192 * 256], d_h2l[8192 * 256];
__device__ __half d_l0h[8192 * 512], d_l0l[8192 * 512];   // l0 fp16 pair
__device__ int   d_idx[8192 * 8];
__device__ float d_Q[8192 * 1024];
__device__ float d_R[8192 * 1024];
__device__ float d_mx[8192 * 1024];                   // raw max-over-k scratch
__device__ __half d_Ah[65536 * 1024];                 // fp16 hi (expanded)
__device__ __half d_Al[65536 * 1024];                 // fp16 lo (expanded)
__device__ __half d_W2h[256 * 64],     d_W2l[256 * 64];
__device__ __half d_WA1h[512 * 512],   d_WA1l[512 * 512];
__device__ __half d_WA2h[512 * 512],   d_WA2l[512 * 512];
__device__ __half d_WB1h[1024 * 1024], d_WB1l[1024 * 1024];
__device__ __half d_WB2h[1024 * 1024], d_WB2l[1024 * 1024];
__device__ float d_sum[1024];
__device__ float d_ss[1024];

// ================= PTX helpers (arch-neutral, sm_80+) ===========================
__device__ __forceinline__ uint32_t smem_u32(const void* p) {
    uint32_t a;
    asm("{ .reg .u64 t; cvta.to.shared.u64 t, %1; cvt.u32.u64 %0, t; }" : "=r"(a) : "l"(p));
    return a;
}
__device__ __forceinline__ void cpa16(uint32_t s, const void* g) {
    asm volatile("cp.async.cg.shared.global [%0], [%1], 16;" :: "r"(s), "l"(g));
}
#define CP_COMMIT() asm volatile("cp.async.commit_group;" ::: "memory")
#define CP_WAIT0()  asm volatile("cp.async.wait_group 0;" ::: "memory")
#define CP_WAIT1()  asm volatile("cp.async.wait_group 1;" ::: "memory")

#define LDSM4(r0, r1, r2, r3, a) \
    asm volatile("ldmatrix.sync.aligned.m8n8.x4.shared.b16 {%0,%1,%2,%3}, [%4];" \
                 : "=r"(r0), "=r"(r1), "=r"(r2), "=r"(r3) : "r"(a))

#define MMA16816(c, a, b) \
    asm volatile("mma.sync.aligned.m16n8k16.row.col.f32.f16.f16.f32 " \
                 "{%0,%1,%2,%3}, {%4,%5,%6,%7}, {%8,%9}, {%0,%1,%2,%3};" \
                 : "+f"((c)[0]), "+f"((c)[1]), "+f"((c)[2]), "+f"((c)[3]) \
                 : "r"((a)[0]), "r"((a)[1]), "r"((a)[2]), "r"((a)[3]), \
                   "r"((b)[0]), "r"((b)[1]))

// ================= HMMA split-fp16 GEMM =========================================
// C[M,N](fp32) = (Ah+Al)[M,K] @ (Bh+Bl)[N,K]^T  via 3 fp16 products (AlBl dropped).
// CTA tile 128(M) x 256(N), BK=32, 3-stage cp.async pipeline.
// 8 warps, 2(m) x 4(n) grid of 64x64 warp tiles (high smem-reuse).
// Smem rows padded to 40 halves (80B) -> ldmatrix conflict-free.
// Modes: maxout != nullptr -> fused raw max over k=8 groups (no C write) + stats.
//        else C write, optional fused stats.
#define GBK 32
#define GA_LO  10240u                 // Al offset   (A: 128 * 80 B)
#define GB_HI  20480u                 // Bh offset
#define GB_LO  40960u                 // Bl offset   (B: 256 * 80 B)
#define GSTAGE 61440u
#define GSMEM_DYN 184320

__device__ __forceinline__ void g_load_stage(uint32_t st,
        const __half* __restrict__ Ah, const __half* __restrict__ Al, int lda,
        const __half* __restrict__ Bh, const __half* __restrict__ Bl, int ldb,
        int bm, int bn, int kc, int tid) {
#pragma unroll
    for (int t = 0; t < 2; t++) {                 // A: 512 chunks of 16B (hi & lo)
        int i = tid + t * 256;
        int row = i >> 2, cg = i & 3;
        uint32_t off = (uint32_t)(row * 80 + cg * 16);
        size_t ga = (size_t)(bm + row) * lda + kc + cg * 8;
        cpa16(st + off, Ah + ga);
        cpa16(st + GA_LO + off, Al + ga);
    }
#pragma unroll
    for (int t = 0; t < 4; t++) {                 // B: 1024 chunks of 16B (hi & lo)
        int i = tid + t * 256;
        int row = i >> 2, cg = i & 3;
        uint32_t off = (uint32_t)(row * 80 + cg * 16);
        size_t gb = (size_t)(bn + row) * ldb + kc + cg * 8;
        cpa16(st + GB_HI + off, Bh + gb);
        cpa16(st + GB_LO + off, Bl + gb);
    }
}

__global__ void __launch_bounds__(256, 1)
gemm_hmma_kernel(const __half* __restrict__ Ah, const __half* __restrict__ Al, int lda,
                 const __half* __restrict__ Bh, const __half* __restrict__ Bl, int ldb,
                 float* __restrict__ C, float* __restrict__ maxout, int ldc, int K,
                 float* __restrict__ gsum, float* __restrict__ gss) {
    extern __shared__ char smem[];
    __shared__ float s_sum[256], s_ss[256];
    const int tid = threadIdx.x;
    const int lane = tid & 31, wid = tid >> 5;
    const int wm = wid & 1, wn = wid >> 1;           // 2 x 4 warp grid, 64x64 tiles
    const int bm = blockIdx.y * 128, bn = blockIdx.x * 256;
    const uint32_t sb = smem_u32(smem);

    if (gsum) { s_sum[tid] = 0.f; s_ss[tid] = 0.f; }

    float acc[4][8][4];
#pragma unroll
    for (int i = 0; i < 4; i++)
#pragma unroll
        for (int j = 0; j < 8; j++)
#pragma unroll
            for (int v = 0; v < 4; v++) acc[i][j][v] = 0.f;

    // ldmatrix base addresses
    const uint32_t a_off = (uint32_t)((wm * 64 + (lane & 15)) * 80 + (lane >> 4) * 16);
    const int b_n = wn * 64 + (lane & 7) + ((lane >> 4) << 3);
    const uint32_t b_koff = (uint32_t)(((lane >> 3) & 1) * 16);

    const int NC = K / GBK;

    g_load_stage(sb, Ah, Al, lda, Bh, Bl, ldb, bm, bn, 0, tid);
    CP_COMMIT();
    if (NC > 1) {
        g_load_stage(sb + GSTAGE, Ah, Al, lda, Bh, Bl, ldb, bm, bn, GBK, tid);
        CP_COMMIT();
    }

    for (int c = 0; c < NC; c++) {
        if (c + 1 < NC) CP_WAIT1(); else CP_WAIT0();
        __syncthreads();
        if (c + 2 < NC) {
            g_load_stage(sb + (uint32_t)((c + 2) % 3) * GSTAGE, Ah, Al, lda, Bh, Bl, ldb,
                         bm, bn, (c + 2) * GBK, tid);
            CP_COMMIT();
        }
        uint32_t st = sb + (uint32_t)(c % 3) * GSTAGE;
#pragma unroll
        for (int kk = 0; kk < 2; kk++) {              // two k16 steps in BK=32
            uint32_t kb = (uint32_t)(kk * 32);        // bytes
            uint32_t bh[8][2], bl[8][2];
#pragma unroll
            for (int p = 0; p < 4; p++) {
                uint32_t ba = st + GB_HI + (uint32_t)((b_n + p * 16) * 80) + b_koff + kb;
                LDSM4(bh[2 * p][0], bh[2 * p][1], bh[2 * p + 1][0], bh[2 * p + 1][1], ba);
                LDSM4(bl[2 * p][0], bl[2 * p][1], bl[2 * p + 1][0], bl[2 * p + 1][1],
                      ba + (GB_LO - GB_HI));
            }
#pragma unroll
            for (int mt = 0; mt < 4; mt++) {
                uint32_t ah[4], al[4];
                uint32_t aa = st + a_off + (uint32_t)(mt * 16 * 80) + kb;
                LDSM4(ah[0], ah[1], ah[2], ah[3], aa);
                LDSM4(al[0], al[1], al[2], al[3], aa + GA_LO);
#pragma unroll
                for (int nt = 0; nt < 8; nt++) {
                    MMA16816(acc[mt][nt], ah, bh[nt]);
                    MMA16816(acc[mt][nt], ah, bl[nt]);
                    MMA16816(acc[mt][nt], al, bh[nt]);
                }
            }
        }
    }

    // ---------------- epilogue -------------------------------------------------
    if (maxout) {
        // fused raw max over k=8 groups: each m16 frag holds rows r(lane>>2) and r+8;
        // shfl over lane>>2 (xor 4,8,16) reduces the 8-row group.
#pragma unroll
        for (int mt = 0; mt < 4; mt++) {
            int gA = (bm + wm * 64 + mt * 16) >> 3;   // output group rows gA, gA+1
#pragma unroll
            for (int nt = 0; nt < 8; nt++) {
                float m0 = acc[mt][nt][0], m1 = acc[mt][nt][1];
                float m2 = acc[mt][nt][2], m3 = acc[mt][nt][3];
#pragma unroll
                for (int off = 4; off < 32; off <<= 1) {
                    m0 = fmaxf(m0, __shfl_xor_sync(0xFFFFFFFFu, m0, off));
                    m1 = fmaxf(m1, __shfl_xor_sync(0xFFFFFFFFu, m1, off));
                    m2 = fmaxf(m2, __shfl_xor_sync(0xFFFFFFFFu, m2, off));
                    m3 = fmaxf(m3, __shfl_xor_sync(0xFFFFFFFFu, m3, off));
                }
                if (lane < 4) {
                    int col = bn + wn * 64 + nt * 8 + lane * 2;
                    float2 v0 = { m0, m1 }, v1 = { m2, m3 };
                    *(float2*)(maxout + (size_t)gA * ldc + col) = v0;
                    *(float2*)(maxout + (size_t)(gA + 1) * ldc + col) = v1;
                }
            }
        }
    } else {
#pragma unroll
        for (int mt = 0; mt < 4; mt++) {
            int row = bm + wm * 64 + mt * 16 + (lane >> 2);
#pragma unroll
            for (int nt = 0; nt < 8; nt++) {
                int col = bn + wn * 64 + nt * 8 + (lane & 3) * 2;
                float2 v0 = { acc[mt][nt][0], acc[mt][nt][1] };
                float2 v1 = { acc[mt][nt][2], acc[mt][nt][3] };
                *(float2*)(C + (size_t)row * ldc + col) = v0;
                *(float2*)(C + (size_t)(row + 8) * ldc + col) = v1;
            }
        }
    }
    if (gsum) {
#pragma unroll
        for (int nt = 0; nt < 8; nt++) {
            float se = 0.f, so = 0.f, qe = 0.f, qo = 0.f;
#pragma unroll
            for (int mt = 0; mt < 4; mt++) {
                float e0 = acc[mt][nt][0], e1 = acc[mt][nt][1];
                float e2 = acc[mt][nt][2], e3 = acc[mt][nt][3];
                se += e0 + e2; so += e1 + e3;
                qe += e0 * e0 + e2 * e2; qo += e1 * e1 + e3 * e3;
            }
#pragma unroll
            for (int off = 4; off < 32; off <<= 1) {
                se += __shfl_xor_sync(0xFFFFFFFFu, se, off);
                so += __shfl_xor_sync(0xFFFFFFFFu, so, off);
                qe += __shfl_xor_sync(0xFFFFFFFFu, qe, off);
                qo += __shfl_xor_sync(0xFFFFFFFFu, qo, off);
            }
            if (lane < 4) {
                int cl = wn * 64 + nt * 8 + lane * 2;
                atomicAdd(&s_sum[cl], se);     atomicAdd(&s_sum[cl + 1], so);
                atomicAdd(&s_ss[cl], qe);      atomicAdd(&s_ss[cl + 1], qo);
            }
        }
        __syncthreads();
        atomicAdd(&gsum[bn + tid], s_sum[tid]);
        atomicAdd(&gss[bn + tid], s_ss[tid]);
    }
}

// ================= small elementwise / stats kernels ============================
__global__ void lin1_kernel(const float* __restrict__ xyz, const float* __restrict__ W1,
                            float* __restrict__ out) {
    int t = blockIdx.x * blockDim.x + threadIdx.x;
    int r = t >> 6, o = t & 63;
    float x0 = xyz[r * 3 + 0], x1 = xyz[r * 3 + 1], x2 = xyz[r * 3 + 2];
    out[t] = x0 * W1[o * 3 + 0] + x1 * W1[o * 3 + 1] + x2 * W1[o * 3 + 2];
}

__global__ void zero_stats_kernel(float* __restrict__ s, float* __restrict__ q) {
    int t = blockIdx.x * blockDim.x + threadIdx.x;
    if (t < 1024) { s[t] = 0.f; q[t] = 0.f; }
}

__global__ void colstats_kernel(const float* __restrict__ x, int M, int C,
                                float* __restrict__ sum, float* __restrict__ ss) {
    int c = blockIdx.y * blockDim.x + threadIdx.x;
    if (c >= C) return;
    size_t r0 = (size_t)blockIdx.x * 512;
    const float* p = x + r0 * C + c;
    float s = 0.f, q = 0.f;
    for (int r = 0; r < 512; r++) { float v = p[(size_t)r * C]; s += v; q += v * v; }
    atomicAdd(&sum[c], s);
    atomicAdd(&ss[c], q);
}

__device__ __forceinline__ uint32_t pk_h2(float a, float b) {
    __half2 t = __floats2half2_rn(a, b);
    return *(uint32_t*)&t;
}

// BN + ReLU + hi/lo fp16 split (reads fp32 once, writes fp16 pair).
__global__ void bnrelu_split_kernel(const float* __restrict__ x,
                                    const float* __restrict__ sum, const float* __restrict__ ss,
                                    const float* __restrict__ g, const float* __restrict__ bta,
                                    __half* __restrict__ hi, __half* __restrict__ lo,
                                    int Mstat, int Mrows, int C) {
    int t = blockIdx.x * blockDim.x + threadIdx.x;
    int C4 = C >> 2;
    if (t >= Mrows * C4) return;
    int c = (t % C4) << 2;
    float invM = 1.0f / (float)Mstat;
    float4 v = ((const float4*)x)[t];
    float vv[4] = { v.x, v.y, v.z, v.w };
    float o[4];
#pragma unroll
    for (int i = 0; i < 4; i++) {
        float m = sum[c + i] * invM;
        float var = ss[c + i] * invM - m * m;
        float sc = g[c + i] * rsqrtf(var + BN_EPS);
        o[i] = fmaxf((vv[i] - m) * sc + bta[c + i], 0.f);
    }
    float h[4];
#pragma unroll
    for (int i = 0; i < 4; i++) h[i] = __half2float(__float2half_rn(o[i]));
    uint2 H = { pk_h2(o[0], o[1]), pk_h2(o[2], o[3]) };
    uint2 L = { pk_h2(o[0] - h[0], o[1] - h[1]), pk_h2(o[2] - h[2], o[3] - h[3]) };
    ((uint2*)hi)[t] = H;
    ((uint2*)lo)[t] = L;
}

// plain hi/lo split (weights)
__global__ void split_kernel(const float* __restrict__ x,
                             __half* __restrict__ hi, __half* __restrict__ lo, int n4) {
    int t = blockIdx.x * blockDim.x + threadIdx.x;
    if (t >= n4) return;
    float4 v = ((const float4*)x)[t];
    float o[4] = { v.x, v.y, v.z, v.w };
    float h[4];
#pragma unroll
    for (int i = 0; i < 4; i++) h[i] = __half2float(__float2half_rn(o[i]));
    uint2 H = { pk_h2(o[0], o[1]), pk_h2(o[2], o[3]) };
    uint2 L = { pk_h2(o[0] - h[0], o[1] - h[1]), pk_h2(o[2] - h[2], o[3] - h[3]) };
    ((uint2*)hi)[t] = H;
    ((uint2*)lo)[t] = L;
}

// kNN: k=8 smallest (stable ties, matches top_k(-d2))
__global__ void knn_kernel(const float* __restrict__ xyz, int* __restrict__ idx) {
    __shared__ float sx[1024], sy[1024], sz[1024], sq[1024];
    int b = blockIdx.y, tid = threadIdx.x;
    for (int i = tid; i < 1024; i += 256) {
        float x = xyz[((b << 10) + i) * 3 + 0];
        float y = xyz[((b << 10) + i) * 3 + 1];
        float z = xyz[((b << 10) + i) * 3 + 2];
        sx[i] = x; sy[i] = y; sz[i] = z;
        sq[i] = x * x + y * y + z * z;
    }
    __syncthreads();
    int n = blockIdx.x * 256 + tid;
    float qx = sx[n], qy = sy[n], qz = sz[n], qs = sq[n];
    float bd[8]; int bi[8];
#pragma unroll
    for (int j = 0; j < 8; j++) { bd[j] = 3.4e38f; bi[j] = 0; }
    for (int m = 0; m < 1024; m++) {
        float d2 = qs + sq[m] - 2.f * (qx * sx[m] + qy * sy[m] + qz * sz[m]);
        if (d2 < bd[7]) {
            bd[7] = d2; bi[7] = m;
#pragma unroll
            for (int j = 7; j > 0; j--) {
                if (bd[j] < bd[j - 1]) {
                    float td = bd[j]; bd[j] = bd[j - 1]; bd[j - 1] = td;
                    int ti = bi[j]; bi[j] = bi[j - 1]; bi[j - 1] = ti;
                }
            }
        }
    }
#pragma unroll
    for (int j = 0; j < 8; j++) idx[((b << 10) + n) * 8 + j] = bi[j];
}

// expand stats only (no materialization): o = Q[idx]-Qc+Rc, column sum/sumsq.
// grid: (65536/256, C4/128), block 128.
__global__ void expand_stats_kernel(const float4* __restrict__ Q, const float4* __restrict__ R,
                                    const int* __restrict__ idx, int C4,
                                    float* __restrict__ gsum, float* __restrict__ gss) {
    __shared__ int sidx[256];
    int c4 = blockIdx.y * 128 + threadIdx.x;
    int r0 = blockIdx.x * 256;
    for (int i = threadIdx.x; i < 256; i += 128) sidx[i] = idx[r0 + i];
    __syncthreads();
    int bn0 = r0 >> 3;
    int b = bn0 >> 10;
    float s[4] = {0.f, 0.f, 0.f, 0.f}, q[4] = {0.f, 0.f, 0.f, 0.f};
    for (int gg = 0; gg < 32; gg++) {
        int bn = bn0 + gg;
        float4 qc = Q[(size_t)bn * C4 + c4];
        float4 rr = R[(size_t)bn * C4 + c4];
        float bx = rr.x - qc.x, by = rr.y - qc.y, bz = rr.z - qc.z, bw = rr.w - qc.w;
#pragma unroll
        for (int k = 0; k < 8; k++) {
            int src = (b << 10) + sidx[gg * 8 + k];
            float4 qa = Q[(size_t)src * C4 + c4];
            float ox = qa.x + bx, oy = qa.y + by, oz = qa.z + bz, ow = qa.w + bw;
            s[0] += ox; s[1] += oy; s[2] += oz; s[3] += ow;
            q[0] += ox * ox; q[1] += oy * oy; q[2] += oz * oz; q[3] += ow * ow;
        }
    }
    int c = c4 << 2;
#pragma unroll
    for (int i = 0; i < 4; i++) { atomicAdd(&gsum[c + i], s[i]); atomicAdd(&gss[c + i], q[i]); }
}

// expand recompute + BN + ReLU + hi/lo fp16 split (writes only fp16 pairs).
__global__ void expand_bnrelu_split_kernel(
        const float4* __restrict__ Q, const float4* __restrict__ R,
        const int* __restrict__ idx, int C4,
        const float* __restrict__ sum, const float* __restrict__ ss,
        const float* __restrict__ g, const float* __restrict__ bta,
        __half* __restrict__ hi, __half* __restrict__ lo) {
    __shared__ int sidx[256];
    int c4 = blockIdx.y * 128 + threadIdx.x;
    int r0 = blockIdx.x * 256;
    for (int i = threadIdx.x; i < 256; i += 128) sidx[i] = idx[r0 + i];
    __syncthreads();
    int bn0 = r0 >> 3;
    int b = bn0 >> 10;
    const float invM = 1.0f / 65536.0f;
    int c = c4 << 2;
    float m[4], sc[4], bb[4];
#pragma unroll
    for (int i = 0; i < 4; i++) {
        m[i] = sum[c + i] * invM;
        float var = ss[c + i] * invM - m[i] * m[i];
        sc[i] = g[c + i] * rsqrtf(var + BN_EPS);
        bb[i] = bta[c + i];
    }
    for (int gg = 0; gg < 32; gg++) {
        int bn = bn0 + gg;
        float4 qc = Q[(size_t)bn * C4 + c4];
        float4 rr = R[(size_t)bn * C4 + c4];
        float bx = rr.x - qc.x, by = rr.y - qc.y, bz = rr.z - qc.z, bw = rr.w - qc.w;
#pragma unroll
        for (int k = 0; k < 8; k++) {
            int row = bn * 8 + k;
            int src = (b << 10) + sidx[gg * 8 + k];
            float4 qa = Q[(size_t)src * C4 + c4];
            float o[4] = { qa.x + bx, qa.y + by, qa.z + bz, qa.w + bw };
            float h[4];
#pragma unroll
            for (int i = 0; i < 4; i++) {
                o[i] = fmaxf((o[i] - m[i]) * sc[i] + bb[i], 0.f);
                h[i] = __half2float(__float2half_rn(o[i]));
            }
            uint2 H = { pk_h2(o[0], o[1]), pk_h2(o[2], o[3]) };
            uint2 L = { pk_h2(o[0] - h[0], o[1] - h[1]), pk_h2(o[2] - h[2], o[3] - h[3]) };
            ((uint2*)hi)[(size_t)row * C4 + c4] = H;
            ((uint2*)lo)[(size_t)row * C4 + c4] = L;
        }
    }
}

// finish: BN+ReLU of raw max (stats over 65536 raw rows) -> fp16 split (l0)
__global__ void finish_split_kernel(const float* __restrict__ mx,
                                    const float* __restrict__ sum, const float* __restrict__ ss,
                                    const float* __restrict__ g, const float* __restrict__ bta,
                                    __half* __restrict__ hi, __half* __restrict__ lo, int C) {
    int t = blockIdx.x * blockDim.x + threadIdx.x;
    int C4 = C >> 2;
    if (t >= 8192 * C4) return;
    int c = (t % C4) << 2;
    const float invM = 1.0f / 65536.0f;
    float4 v = ((const float4*)mx)[t];
    float vv[4] = { v.x, v.y, v.z, v.w };
    float o[4], h[4];
#pragma unroll
    for (int i = 0; i < 4; i++) {
        float m = sum[c + i] * invM;
        float var = ss[c + i] * invM - m * m;
        float sc = g[c + i] * rsqrtf(var + BN_EPS);
        o[i] = fmaxf((vv[i] - m) * sc + bta[c + i], 0.f);
        h[i] = __half2float(__float2half_rn(o[i]));
    }
    uint2 H = { pk_h2(o[0], o[1]), pk_h2(o[2], o[3]) };
    uint2 L = { pk_h2(o[0] - h[0], o[1] - h[1]), pk_h2(o[2] - h[2], o[3] - h[3]) };
    ((uint2*)hi)[t] = H;
    ((uint2*)lo)[t] = L;
}

// finish: BN+ReLU of raw max + transpose to (B, C, N). C=1024.
// grid (32, 32, 8), block (32,8)
__global__ void finish_out_t_kernel(const float* __restrict__ mx,
                                    const float* __restrict__ sum, const float* __restrict__ ss,
                                    const float* __restrict__ g, const float* __restrict__ bta,
                                    float* __restrict__ out) {
    __shared__ float tile[32][33];
    int b = blockIdx.z;
    int n0 = blockIdx.x * 32;
    int c0 = blockIdx.y * 32;
    int c = c0 + threadIdx.x;
    const float invM = 1.0f / 65536.0f;
    float m = sum[c] * invM;
    float var = ss[c] * invM - m * m;
    float sc = g[c] * rsqrtf(var + BN_EPS);
    float bb = bta[c];
#pragma unroll
    for (int j = 0; j < 4; j++) {
        int nl = threadIdx.y + j * 8;
        int bn = (b << 10) + n0 + nl;
        float v = mx[(size_t)bn * 1024 + c];
        tile[threadIdx.x][nl] = fmaxf((v - m) * sc + bb, 0.f);
    }
    __syncthreads();
#pragma unroll
    for (int j = 0; j < 4; j++) {
        int cl = threadIdx.y + j * 8;
        out[((size_t)b * 1024 + c0 + cl) * 1024 + n0 + threadIdx.x] = tile[cl][threadIdx.x];
    }
}

// ================= host orchestration ===========================================
extern "C" void kernel_launch(void* const* d_in, const int* in_sizes, int n_in,
                              void* d_out, int out_size) {
    const float* xyz = (const float*)d_in[0];
    const float* W1  = (const float*)d_in[1];
    const float* g1  = (const float*)d_in[2];
    const float* b1  = (const float*)d_in[3];
    const float* W2  = (const float*)d_in[4];
    const float* g2  = (const float*)d_in[5];
    const float* b2  = (const float*)d_in[6];
    const float* WA1 = (const float*)d_in[7];
    const float* gA1 = (const float*)d_in[8];
    const float* bA1 = (const float*)d_in[9];
    const float* WA2 = (const float*)d_in[10];
    const float* gA2 = (const float*)d_in[11];
    const float* bA2 = (const float*)d_in[12];
    const float* WB1 = (const float*)d_in[13];
    const float* gB1 = (const float*)d_in[14];
    const float* bB1 = (const float*)d_in[15];
    const float* WB2 = (const float*)d_in[16];
    const float* gB2 = (const float*)d_in[17];
    const float* bB2 = (const float*)d_in[18];
    float* out = (float*)d_out;

    float *h1, *h2, *Q, *R, *mx, *sumb, *ssb;
    __half *h1h, *h1l, *h2h, *h2l, *l0h, *l0l, *Ah, *Al;
    __half *W2h, *W2l, *WA1h, *WA1l, *WA2h, *WA2l, *WB1h, *WB1l, *WB2h, *WB2l;
    int* idx;
    cudaGetSymbolAddress((void**)&h1, d_h1);   cudaGetSymbolAddress((void**)&h1h, d_h1h);
    cudaGetSymbolAddress((void**)&h1l, d_h1l); cudaGetSymbolAddress((void**)&h2, d_h2);
    cudaGetSymbolAddress((void**)&h2h, d_h2h); cudaGetSymbolAddress((void**)&h2l, d_h2l);
    cudaGetSymbolAddress((void**)&l0h, d_l0h); cudaGetSymbolAddress((void**)&l0l, d_l0l);
    cudaGetSymbolAddress((void**)&idx, d_idx); cudaGetSymbolAddress((void**)&Q, d_Q);
    cudaGetSymbolAddress((void**)&R, d_R);     cudaGetSymbolAddress((void**)&mx, d_mx);
    cudaGetSymbolAddress((void**)&Ah, d_Ah);   cudaGetSymbolAddress((void**)&Al, d_Al);
    cudaGetSymbolAddress((void**)&W2h, d_W2h);   cudaGetSymbolAddress((void**)&W2l, d_W2l);
    cudaGetSymbolAddress((void**)&WA1h, d_WA1h); cudaGetSymbolAddress((void**)&WA1l, d_WA1l);
    cudaGetSymbolAddress((void**)&WA2h, d_WA2h); cudaGetSymbolAddress((void**)&WA2l, d_WA2l);
    cudaGetSymbolAddress((void**)&WB1h, d_WB1h); cudaGetSymbolAddress((void**)&WB1l, d_WB1l);
    cudaGetSymbolAddress((void**)&WB2h, d_WB2h); cudaGetSymbolAddress((void**)&WB2l, d_WB2l);
    cudaGetSymbolAddress((void**)&sumb, d_sum);  cudaGetSymbolAddress((void**)&ssb, d_ss);

    cudaFuncSetAttribute(gemm_hmma_kernel, cudaFuncAttributeMaxDynamicSharedMemorySize,
                         GSMEM_DYN);
    const int T = 256;

    // weight splits
    split_kernel<<<16, T>>>(W2, W2h, W2l, 256 * 64 / 4);
    split_kernel<<<256, T>>>(WA1, WA1h, WA1l, 512 * 512 / 4);
    split_kernel<<<256, T>>>(WA2, WA2h, WA2l, 512 * 512 / 4);
    split_kernel<<<1024, T>>>(WB1, WB1h, WB1l, 1024 * 1024 / 4);
    split_kernel<<<1024, T>>>(WB2, WB2h, WB2l, 1024 * 1024 / 4);

    // kNN
    knn_kernel<<<dim3(4, 8), T>>>(xyz, idx);

    // layer 1: h1 = bn_relu(xyz @ W1^T), split
    lin1_kernel<<<2048, T>>>(xyz, W1, h1);
    zero_stats_kernel<<<4, T>>>(sumb, ssb);
    colstats_kernel<<<dim3(16, 1), T>>>(h1, 8192, 64, sumb, ssb);
    bnrelu_split_kernel<<<512, T>>>(h1, sumb, ssb, g1, b1, h1h, h1l, 8192, 8192, 64);

    // layer 2: h2 = h1 @ W2^T (+stats), bn_relu split  (N=256 -> 1 block x)
    zero_stats_kernel<<<4, T>>>(sumb, ssb);
    gemm_hmma_kernel<<<dim3(1, 64), T, GSMEM_DYN>>>(h1h, h1l, 64, W2h, W2l, 64,
                                                    h2, nullptr, 256, 64, sumb, ssb);
    bnrelu_split_kernel<<<2048, T>>>(h2, sumb, ssb, g2, b2, h2h, h2l, 8192, 8192, 256);

    // ---- local_op A ----
    gemm_hmma_kernel<<<dim3(2, 64), T, GSMEM_DYN>>>(h2h, h2l, 256, WA1h, WA1l, 512,
                                                    Q, nullptr, 512, 256, nullptr, nullptr);
    gemm_hmma_kernel<<<dim3(2, 64), T, GSMEM_DYN>>>(h2h, h2l, 256, WA1h + 256, WA1l + 256, 512,
                                                    R, nullptr, 512, 256, nullptr, nullptr);
    zero_stats_kernel<<<4, T>>>(sumb, ssb);
    expand_stats_kernel<<<dim3(256, 1), 128>>>((const float4*)Q, (const float4*)R, idx,
                                               128, sumb, ssb);
    expand_bnrelu_split_kernel<<<dim3(256, 1), 128>>>((const float4*)Q, (const float4*)R, idx,
                                                      128, sumb, ssb, gA1, bA1, Ah, Al);
    zero_stats_kernel<<<4, T>>>(sumb, ssb);
    gemm_hmma_kernel<<<dim3(2, 512), T, GSMEM_DYN>>>(Ah, Al, 512, WA2h, WA2l, 512,
                                                     nullptr, mx, 512, 512, sumb, ssb);
    finish_split_kernel<<<4096, T>>>(mx, sumb, ssb, gA2, bA2, l0h, l0l, 512);

    // ---- local_op B ----
    gemm_hmma_kernel<<<dim3(4, 64), T, GSMEM_DYN>>>(l0h, l0l, 512, WB1h, WB1l, 1024,
                                                    Q, nullptr, 1024, 512, nullptr, nullptr);
    gemm_hmma_kernel<<<dim3(4, 64), T, GSMEM_DYN>>>(l0h, l0l, 512, WB1h + 512, WB1l + 512, 1024,
                                                    R, nullptr, 1024, 512, nullptr, nullptr);
    zero_stats_kernel<<<4, T>>>(sumb, ssb);
    expand_stats_kernel<<<dim3(256, 2), 128>>>((const float4*)Q, (const float4*)R, idx,
                                               256, sumb, ssb);
    expand_bnrelu_split_kernel<<<dim3(256, 2), 128>>>((const float4*)Q, (const float4*)R, idx,
                                                      256, sumb, ssb, gB1, bB1, Ah, Al);
    zero_stats_kernel<<<4, T>>>(sumb, ssb);
    gemm_hmma_kernel<<<dim3(4, 512), T, GSMEM_DYN>>>(Ah, Al, 1024, WB2h, WB2l, 1024,
                                                     nullptr, mx, 1024, 1024, sumb, ssb);
    finish_out_t_kernel<<<dim3(32, 32, 8), dim3(32, 8)>>>(mx, sumb, ssb, gB2, bB2, out);
}